// round 13
// baseline (speedup 1.0000x reference)
#include <cuda_runtime.h>
#include <cuda_bf16.h>
#include <cuda_fp16.h>
#include <cstdint>

#define B_   2
#define C_   256
#define CI_  128
#define T_   16
#define H_   28
#define W_   28
#define N_   12544
#define HS_  14
#define WS_  14
#define NS_  3136

typedef unsigned long long u64;

// ---------------- scratch (device globals) -------------------------------------
__device__ __align__(16) __nv_bfloat16 d_xT_h[B_*N_*C_],  d_xT_l[B_*N_*C_];
__device__ __align__(16) __nv_bfloat16 d_mT_h[B_*N_*C_],  d_mT_l[B_*N_*C_];
__device__ __align__(16) __nv_bfloat16 d_pgw_h[2*CI_*C_], d_pgw_l[2*CI_*C_];
__device__ __align__(16) __nv_bfloat16 d_tw_h[CI_*C_],    d_tw_l[CI_*C_];
__device__ __align__(16) __nv_bfloat16 d_Ww_h[C_*CI_],    d_Ww_l[C_*CI_];
__device__ float d_pg_bias[2*CI_];
__device__ __align__(16) __half d_thT[B_*N_*CI_];                    // fp16 single
__device__ __align__(16) float d_pgN[B_*N_*2*CI_];
__device__ __align__(16) __half d_phiP[B_*NS_*CI_];                  // fp16 single
__device__ __align__(16) float d_gpool[B_*NS_*CI_];
__device__ __align__(16) __half d_gsT[B_*CI_*NS_];                   // g transposed, fp16, UNSCALED
__device__ __align__(16) __nv_bfloat16 d_ef_h[(size_t)B_*N_*NS_];   // exp(f) bf16 (157 MB)
__device__ __align__(16) __half d_W[(size_t)B_*N_*NS_];             // softmax weights fp16 (79 MB)
__device__ float d_colsum[B_*NS_];
__device__ __align__(16) float d_yF[B_*N_*CI_];
__device__ __align__(16) __nv_bfloat16 d_y_h[B_*N_*CI_], d_y_l[B_*N_*CI_];
__device__ __align__(16) float d_wy[B_*C_*N_];
__device__ float d_bnsum[C_], d_bnsumsq[C_];
__device__ float d_bnscale[C_], d_bnbias[C_];

// ---------------- PTX helpers ---------------------------------------------------
__device__ __forceinline__ uint32_t smem_u32(const void* p) {
    uint32_t a;
    asm("{ .reg .u64 t; cvta.to.shared.u64 t, %1; cvt.u32.u64 %0, t; }" : "=r"(a) : "l"(p));
    return a;
}
__device__ __forceinline__ void cpa16(uint32_t d, const void* s, int sz) {
    asm volatile("cp.async.ca.shared.global [%0], [%1], 16, %2;" :: "r"(d), "l"(s), "r"(sz));
}
__device__ __forceinline__ void cp_commit() { asm volatile("cp.async.commit_group;" ::: "memory"); }
__device__ __forceinline__ void cp_wait0()  { asm volatile("cp.async.wait_group 0;"  ::: "memory"); }

__device__ __forceinline__ void ldm4(uint32_t* r, uint32_t a) {
    asm volatile("ldmatrix.sync.aligned.m8n8.x4.shared.b16 {%0,%1,%2,%3}, [%4];"
                 : "=r"(r[0]), "=r"(r[1]), "=r"(r[2]), "=r"(r[3]) : "r"(a));
}
__device__ __forceinline__ void mma_bf16(float* c, const uint32_t* a, uint32_t b0, uint32_t b1) {
    asm volatile("mma.sync.aligned.m16n8k16.row.col.f32.bf16.bf16.f32 "
                 "{%0,%1,%2,%3}, {%4,%5,%6,%7}, {%8,%9}, {%0,%1,%2,%3};"
                 : "+f"(c[0]), "+f"(c[1]), "+f"(c[2]), "+f"(c[3])
                 : "r"(a[0]), "r"(a[1]), "r"(a[2]), "r"(a[3]), "r"(b0), "r"(b1));
}
__device__ __forceinline__ void mma_fp16(float* c, const uint32_t* a, uint32_t b0, uint32_t b1) {
    asm volatile("mma.sync.aligned.m16n8k16.row.col.f32.f16.f16.f32 "
                 "{%0,%1,%2,%3}, {%4,%5,%6,%7}, {%8,%9}, {%0,%1,%2,%3};"
                 : "+f"(c[0]), "+f"(c[1]), "+f"(c[2]), "+f"(c[3])
                 : "r"(a[0]), "r"(a[1]), "r"(a[2]), "r"(a[3]), "r"(b0), "r"(b1));
}
__device__ __forceinline__ void store_split2(__nv_bfloat16* hi, __nv_bfloat16* lo,
                                             size_t o, float v0, float v1) {
    __nv_bfloat16 h0 = __float2bfloat16(v0), h1 = __float2bfloat16(v1);
    __nv_bfloat162 hv; hv.x = h0; hv.y = h1;
    __nv_bfloat162 lv;
    lv.x = __float2bfloat16(v0 - __bfloat162float(h0));
    lv.y = __float2bfloat16(v1 - __bfloat162float(h1));
    *(__nv_bfloat162*)(hi + o) = hv;
    *(__nv_bfloat162*)(lo + o) = lv;
}

// ---------------- generic split-bf16/fp16 HMMA GEMM ------------------------------
// AS: A single   BS: B single   HALF: fp16 MMA for Ah*Bh
// products: Ah*Bh always; +Ah*Bl if !BS; +Al*Bh if !AS
// EPI 0: fp32 store (+biasCol/+biasRow)
// EPI 1: split-bf16 store (+biasCol)
// EPI 2: exp -> bf16 quantize -> colsum atomics (from quantized) + staged bf16 store
// EPI 3: fp32 atomicAdd (split-K partials)
// EPI 4: fp32 store (+biasRow) + per-channel sum/sumsq atomics (fused BN stats)
// EPI 5: single-fp16 store (+biasCol)
#define TROW 80
#define TILE_BYTES (128*TROW)
#define OFF_AH 0
#define OFF_AL (TILE_BYTES)
#define OFF_BH (2*TILE_BYTES)
#define OFF_BL (3*TILE_BYTES)
#define BUF_BYTES (4*TILE_BYTES)
#define SMEM_TOT (2*BUF_BYTES)
#define EROW 136

template <int AS, int BS>
__device__ __forceinline__ void copy_chunk(uint32_t sb, int buf,
    const __nv_bfloat16* Ah, const __nv_bfloat16* Al, int i0,
    const __nv_bfloat16* Bh, const __nv_bfloat16* Bl, int j0, int Nn,
    int K, int k0, int tid)
{
    uint32_t base = sb + buf * BUF_BYTES;
#pragma unroll
    for (int i = 0; i < 2; i++) {
        int e = tid + i * 256;
        int r = e >> 2, seg = e & 3;
        uint32_t doff = r * TROW + seg * 16;
        size_t asrc = (size_t)(i0 + r) * K + k0 + seg * 8;
        cpa16(base + OFF_AH + doff, Ah + asrc, 16);
        if (!AS) cpa16(base + OFF_AL + doff, Al + asrc, 16);
        int brow = j0 + r;
        int sz = (brow < Nn) ? 16 : 0;
        int brc = (brow < Nn) ? brow : (Nn - 1);
        size_t bsrc = (size_t)brc * K + k0 + seg * 8;
        cpa16(base + OFF_BH + doff, Bh + bsrc, sz);
        if (!BS) cpa16(base + OFF_BL + doff, Bl + bsrc, sz);
    }
}

template <int EPI, int AS, int BS, int HALF>
__global__ void __launch_bounds__(256, 2)
mma_gemm(const __nv_bfloat16* __restrict__ Ah, const __nv_bfloat16* __restrict__ Al, size_t strA,
         const __nv_bfloat16* __restrict__ Bh, const __nv_bfloat16* __restrict__ Bl, size_t strB,
         int M, int Nn, int K, int ksplits,
         const float* __restrict__ biasCol, const float* __restrict__ biasRow,
         float* __restrict__ outF,
         __nv_bfloat16* __restrict__ outHi, __nv_bfloat16* __restrict__ outLo,
         size_t strO, int ldO,
         float* __restrict__ colsum,
         float* __restrict__ bnsum, float* __restrict__ bnsumsq)
{
    extern __shared__ __align__(128) char smem[];
    const uint32_t sb = smem_u32(smem);
    const int tid = threadIdx.x, lane = tid & 31, wid = tid >> 5;
    const int wm = wid >> 2, wn = wid & 3;
    const int z  = blockIdx.z;
    const int ksid = blockIdx.x % ksplits;
    const int i0 = blockIdx.y * 128, j0 = (blockIdx.x / ksplits) * 128;
    const int kLen = K / ksplits;      // must be a multiple of 32
    const int kOff = ksid * kLen;

    const __nv_bfloat16* Ahz = Ah + (size_t)z * strA;
    const __nv_bfloat16* Alz = Al + (size_t)z * strA;
    const __nv_bfloat16* Bhz = Bh + (size_t)z * strB;
    const __nv_bfloat16* Blz = Bl + (size_t)z * strB;

    float acc[4][4][4];
#pragma unroll
    for (int a = 0; a < 4; a++)
#pragma unroll
        for (int b = 0; b < 4; b++)
#pragma unroll
            for (int c = 0; c < 4; c++) acc[a][b][c] = 0.f;

    const uint32_t aBase = sb + (uint32_t)((wm * 64 + (lane & 15)) * TROW + (lane >> 4) * 16);
    const uint32_t bBase = sb + (uint32_t)((wn * 32 + (lane & 7) + ((lane & 16) ? 8 : 0)) * TROW
                                           + ((lane & 8) ? 16 : 0));

    const int nch = kLen / 32;
    copy_chunk<AS, BS>(sb, 0, Ahz, Alz, i0, Bhz, Blz, j0, Nn, K, kOff, tid);
    cp_commit();
    for (int ch = 0; ch < nch; ch++) {
        cp_wait0();
        __syncthreads();
        if (ch + 1 < nch) {
            copy_chunk<AS, BS>(sb, (ch + 1) & 1, Ahz, Alz, i0, Bhz, Blz, j0, Nn, K,
                               kOff + (ch + 1) * 32, tid);
            cp_commit();
        }
        const uint32_t buf = (uint32_t)((ch & 1) * BUF_BYTES);
#pragma unroll
        for (int ks = 0; ks < 2; ks++) {
            uint32_t bh[8], bl[8];
#pragma unroll
            for (int grp = 0; grp < 2; grp++) {
                ldm4(&bh[grp * 4], bBase + buf + OFF_BH + grp * (16 * TROW) + ks * 32);
                if (!BS)
                    ldm4(&bl[grp * 4], bBase + buf + OFF_BL + grp * (16 * TROW) + ks * 32);
            }
#pragma unroll
            for (int am = 0; am < 4; am++) {
                uint32_t ah4[4], al4[4];
                ldm4(ah4, aBase + buf + OFF_AH + am * (16 * TROW) + ks * 32);
                if (!AS)
                    ldm4(al4, aBase + buf + OFF_AL + am * (16 * TROW) + ks * 32);
#pragma unroll
                for (int bn = 0; bn < 4; bn++) {
                    if (HALF) mma_fp16(acc[am][bn], ah4, bh[bn * 2], bh[bn * 2 + 1]);
                    else      mma_bf16(acc[am][bn], ah4, bh[bn * 2], bh[bn * 2 + 1]);
                }
                if (!BS) {
#pragma unroll
                    for (int bn = 0; bn < 4; bn++)
                        mma_bf16(acc[am][bn], ah4, bl[bn * 2], bl[bn * 2 + 1]);
                }
                if (!AS) {
#pragma unroll
                    for (int bn = 0; bn < 4; bn++)
                        mma_bf16(acc[am][bn], al4, bh[bn * 2], bh[bn * 2 + 1]);
                }
            }
        }
    }

    // ---- epilogue ----
    const int q    = lane >> 2;
    const int rloc = wm * 64 + q;
    const int cloc = wn * 32 + (lane & 3) * 2;

    if (EPI == 2) {
        __syncthreads();
        __nv_bfloat16* sh = (__nv_bfloat16*)smem;                       // [128][EROW]
        float cs[4][2];
#pragma unroll
        for (int bn = 0; bn < 4; bn++) { cs[bn][0] = 0.f; cs[bn][1] = 0.f; }
#pragma unroll
        for (int am = 0; am < 4; am++) {
            int rl = rloc + am * 16;
#pragma unroll
            for (int bn = 0; bn < 4; bn++) {
                int jl = cloc + bn * 8;
                __nv_bfloat16 h0 = __float2bfloat16(__expf(acc[am][bn][0]));
                __nv_bfloat16 h1 = __float2bfloat16(__expf(acc[am][bn][1]));
                __nv_bfloat16 h2 = __float2bfloat16(__expf(acc[am][bn][2]));
                __nv_bfloat16 h3 = __float2bfloat16(__expf(acc[am][bn][3]));
                cs[bn][0] += __bfloat162float(h0) + __bfloat162float(h2);
                cs[bn][1] += __bfloat162float(h1) + __bfloat162float(h3);
                __nv_bfloat162 hv01; hv01.x = h0; hv01.y = h1;
                __nv_bfloat162 hv23; hv23.x = h2; hv23.y = h3;
                *(__nv_bfloat162*)&sh[rl * EROW + jl]       = hv01;
                *(__nv_bfloat162*)&sh[(rl + 8) * EROW + jl] = hv23;
            }
        }
#pragma unroll
        for (int bn = 0; bn < 4; bn++)
#pragma unroll
            for (int jj = 0; jj < 2; jj++) {
                float v = cs[bn][jj];
                v += __shfl_xor_sync(0xffffffffu, v, 4);
                v += __shfl_xor_sync(0xffffffffu, v, 8);
                v += __shfl_xor_sync(0xffffffffu, v, 16);
                if (q == 0) {
                    int jg = j0 + cloc + bn * 8 + jj;
                    if (jg < Nn) atomicAdd(&colsum[z * Nn + jg], v);
                }
            }
        __syncthreads();
#pragma unroll
        for (int it = 0; it < 8; it++) {
            int e = it * 256 + tid;
            int r = e >> 4, s = e & 15;
            int jg = j0 + s * 8;
            if (jg < Nn) {
                size_t o = (size_t)z * strO + (size_t)(i0 + r) * ldO + jg;
                *(uint4*)(outHi + o) = *(const uint4*)&sh[r * EROW + s * 8];
            }
        }
    } else if (EPI == 1) {
#pragma unroll
        for (int am = 0; am < 4; am++) {
            int ig0 = i0 + rloc + am * 16;
#pragma unroll
            for (int bn = 0; bn < 4; bn++) {
                int jg = j0 + cloc + bn * 8;
                if (jg < Nn) {
                    float bc0 = biasCol ? biasCol[jg]     : 0.f;
                    float bc1 = biasCol ? biasCol[jg + 1] : 0.f;
                    size_t o0 = (size_t)z * strO + (size_t)ig0 * ldO + jg;
                    store_split2(outHi, outLo, o0, acc[am][bn][0] + bc0, acc[am][bn][1] + bc1);
                    store_split2(outHi, outLo, o0 + (size_t)8 * ldO,
                                 acc[am][bn][2] + bc0, acc[am][bn][3] + bc1);
                }
            }
        }
    } else if (EPI == 5) {
        __half* outH = (__half*)outHi;
#pragma unroll
        for (int am = 0; am < 4; am++) {
            int ig0 = i0 + rloc + am * 16;
#pragma unroll
            for (int bn = 0; bn < 4; bn++) {
                int jg = j0 + cloc + bn * 8;
                if (jg < Nn) {
                    float bc0 = biasCol ? biasCol[jg]     : 0.f;
                    float bc1 = biasCol ? biasCol[jg + 1] : 0.f;
                    size_t o0 = (size_t)z * strO + (size_t)ig0 * ldO + jg;
                    __half2 v01; v01.x = __float2half(acc[am][bn][0] + bc0);
                                 v01.y = __float2half(acc[am][bn][1] + bc1);
                    __half2 v23; v23.x = __float2half(acc[am][bn][2] + bc0);
                                 v23.y = __float2half(acc[am][bn][3] + bc1);
                    *(__half2*)(outH + o0) = v01;
                    *(__half2*)(outH + o0 + (size_t)8 * ldO) = v23;
                }
            }
        }
    } else if (EPI == 3) {
#pragma unroll
        for (int am = 0; am < 4; am++) {
            int ig0 = i0 + rloc + am * 16;
#pragma unroll
            for (int bn = 0; bn < 4; bn++) {
                int jg = j0 + cloc + bn * 8;
                if (jg < Nn) {
                    size_t o0 = (size_t)z * strO + (size_t)ig0 * ldO + jg;
                    atomicAdd(outF + o0,     acc[am][bn][0]);
                    atomicAdd(outF + o0 + 1, acc[am][bn][1]);
                    atomicAdd(outF + o0 + (size_t)8 * ldO,     acc[am][bn][2]);
                    atomicAdd(outF + o0 + (size_t)8 * ldO + 1, acc[am][bn][3]);
                }
            }
        }
    } else {  // EPI 0 / 4
#pragma unroll
        for (int am = 0; am < 4; am++) {
            int ig0 = i0 + rloc + am * 16;
            float br0 = biasRow ? biasRow[ig0]     : 0.f;
            float br1 = biasRow ? biasRow[ig0 + 8] : 0.f;
            float sA = 0.f, sqA = 0.f, sB = 0.f, sqB = 0.f;
#pragma unroll
            for (int bn = 0; bn < 4; bn++) {
                int jg = j0 + cloc + bn * 8;
                if (jg < Nn) {
                    float bc0 = biasCol ? biasCol[jg]     : 0.f;
                    float bc1 = biasCol ? biasCol[jg + 1] : 0.f;
                    float v0 = acc[am][bn][0] + bc0 + br0;
                    float v1 = acc[am][bn][1] + bc1 + br0;
                    float v2 = acc[am][bn][2] + bc0 + br1;
                    float v3 = acc[am][bn][3] + bc1 + br1;
                    size_t o0 = (size_t)z * strO + (size_t)ig0 * ldO + jg;
                    *(float2*)(outF + o0) = make_float2(v0, v1);
                    *(float2*)(outF + o0 + (size_t)8 * ldO) = make_float2(v2, v3);
                    if (EPI == 4) {
                        sA += v0 + v1;  sqA += v0 * v0 + v1 * v1;
                        sB += v2 + v3;  sqB += v2 * v2 + v3 * v3;
                    }
                }
            }
            if (EPI == 4) {
                sA  += __shfl_xor_sync(0xffffffffu, sA, 1);
                sA  += __shfl_xor_sync(0xffffffffu, sA, 2);
                sqA += __shfl_xor_sync(0xffffffffu, sqA, 1);
                sqA += __shfl_xor_sync(0xffffffffu, sqA, 2);
                sB  += __shfl_xor_sync(0xffffffffu, sB, 1);
                sB  += __shfl_xor_sync(0xffffffffu, sB, 2);
                sqB += __shfl_xor_sync(0xffffffffu, sqB, 1);
                sqB += __shfl_xor_sync(0xffffffffu, sqB, 2);
                if ((lane & 3) == 0) {
                    atomicAdd(&bnsum[ig0],       sA);
                    atomicAdd(&bnsumsq[ig0],     sqA);
                    atomicAdd(&bnsum[ig0 + 8],   sB);
                    atomicAdd(&bnsumsq[ig0 + 8], sqB);
                }
            }
        }
    }
}

// ---------------- prep / pool / BN kernels --------------------------------------
__global__ void split_weights(const float* __restrict__ g_w, const float* __restrict__ t_w,
                              const float* __restrict__ p_w, const float* __restrict__ W_w)
{
    int i = blockIdx.x * 256 + threadIdx.x;
    int which = blockIdx.y;
    const float* in = (which == 0) ? g_w : (which == 1) ? t_w : (which == 2) ? p_w : W_w;
    __nv_bfloat16* ho = (which == 0) ? (d_pgw_h + CI_ * C_) : (which == 1) ? d_tw_h
                      : (which == 2) ? d_pgw_h : d_Ww_h;
    __nv_bfloat16* lo = (which == 0) ? (d_pgw_l + CI_ * C_) : (which == 1) ? d_tw_l
                      : (which == 2) ? d_pgw_l : d_Ww_l;
    float v = in[i];
    __nv_bfloat16 h = __float2bfloat16(v);
    ho[i] = h;
    lo[i] = __float2bfloat16(v - __bfloat162float(h));
}

__global__ void stack_bias(const float* __restrict__ phi_b, const float* __restrict__ g_b)
{
    int i = threadIdx.x;
    d_pg_bias[i] = (i < CI_) ? phi_b[i] : g_b[i - CI_];
}

__global__ void transpose_split(const float* __restrict__ in,
                                __nv_bfloat16* __restrict__ hi, __nv_bfloat16* __restrict__ lo)
{
    __shared__ float t[32][33];
    int z  = blockIdx.z;
    int n0 = blockIdx.x * 32, c0 = blockIdx.y * 32;
    int tx = threadIdx.x, ty = threadIdx.y;
    const float* ip = in + (size_t)z * C_ * N_;
#pragma unroll
    for (int i = 0; i < 4; i++)
        t[ty + 8 * i][tx] = ip[(size_t)(c0 + ty + 8 * i) * N_ + n0 + tx];
    __syncthreads();
#pragma unroll
    for (int i = 0; i < 4; i++) {
        float v = t[tx][ty + 8 * i];
        __nv_bfloat16 h = __float2bfloat16(v);
        size_t o = ((size_t)z * N_ + n0 + ty + 8 * i) * C_ + c0 + tx;
        hi[o] = h;
        lo[o] = __float2bfloat16(v - __bfloat162float(h));
    }
}

// phi: pooled -> single fp16 (z, NS, CI)
__global__ void pool_phi_k()
{
    int m = blockIdx.x, z = blockIdx.y, ci = threadIdx.x;
    int t  = m / (HS_ * WS_);
    int r  = m % (HS_ * WS_);
    int h2 = r / WS_, w2 = r % WS_;
    int n00 = t * (H_ * W_) + 2 * h2 * W_ + 2 * w2;
    const float* p = d_pgN + (size_t)z * N_ * 2 * CI_ + ci;
    const int ld = 2 * CI_;
    float v = fmaxf(fmaxf(p[(size_t)n00 * ld],        p[(size_t)(n00 + 1) * ld]),
                    fmaxf(p[(size_t)(n00 + W_) * ld], p[(size_t)(n00 + W_ + 1) * ld]));
    d_phiP[((size_t)z * NS_ + m) * CI_ + ci] = __float2half(v);
}

__global__ void pool_g_k()
{
    int m = blockIdx.x, z = blockIdx.y, ci = threadIdx.x;
    int t  = m / (HS_ * WS_);
    int r  = m % (HS_ * WS_);
    int h2 = r / WS_, w2 = r % WS_;
    int n00 = t * (H_ * W_) + 2 * h2 * W_ + 2 * w2;
    const float* p = d_pgN + (size_t)z * N_ * 2 * CI_ + CI_ + ci;
    const int ld = 2 * CI_;
    float v = fmaxf(fmaxf(p[(size_t)n00 * ld],        p[(size_t)(n00 + 1) * ld]),
                    fmaxf(p[(size_t)(n00 + W_) * ld], p[(size_t)(n00 + W_ + 1) * ld]));
    d_gpool[((size_t)z * NS_ + m) * CI_ + ci] = v;
}

// gpool (z, NS, CI) fp32 -> gsT (z, CI, NS) fp16 (UNSCALED — Z folded into W)
__global__ void tr_convert_g()
{
    __shared__ float t[32][33];
    int z  = blockIdx.z;
    int m0 = blockIdx.x * 32, c0 = blockIdx.y * 32;
    int tx = threadIdx.x, ty = threadIdx.y;
#pragma unroll
    for (int i = 0; i < 4; i++)
        t[ty + 8 * i][tx] = d_gpool[((size_t)z * NS_ + m0 + ty + 8 * i) * CI_ + c0 + tx];
    __syncthreads();
#pragma unroll
    for (int i = 0; i < 4; i++) {
        size_t o = ((size_t)z * CI_ + c0 + ty + 8 * i) * NS_ + m0 + tx;
        d_gsT[o] = __float2half(t[tx][ty + 8 * i]);
    }
}

// W = ef / Z  (bf16 -> fp16, ratio cancellation of bf16 quantization)
__global__ void divide_W()
{
    size_t e = (size_t)blockIdx.x * 256 + threadIdx.x;   // each handles 8 elems
    if (e >= (size_t)B_ * N_ * NS_ / 8) return;
    size_t base = e * 8;
    int m   = (int)(base % NS_);
    int row = (int)(base / NS_);
    int z   = row / N_;
    uint4 ev = *(const uint4*)&d_ef_h[base];
    const __nv_bfloat162* eb = (const __nv_bfloat162*)&ev;
    const float* Zp = &d_colsum[z * NS_ + m];
    __half2 w[4];
#pragma unroll
    for (int i = 0; i < 4; i++) {
        float z0 = Zp[2 * i], z1 = Zp[2 * i + 1];
        w[i].x = __float2half(__bfloat162float(eb[i].x) / z0);
        w[i].y = __float2half(__bfloat162float(eb[i].y) / z1);
    }
    *(uint4*)&d_W[base] = *(const uint4*)w;    // FIXED: full 16B store (was uint2)
}

// y fp32 -> split bf16
__global__ void y_convert()
{
    int i2 = blockIdx.x * 256 + threadIdx.x;
    if (i2 >= B_ * N_ * CI_ / 2) return;
    float2 v = *(const float2*)&d_yF[i2 * 2];
    store_split2(d_y_h, d_y_l, (size_t)i2 * 2, v.x, v.y);
}

__global__ void bn_finalize(const float* __restrict__ gamma, const float* __restrict__ beta)
{
    int c = threadIdx.x;
    float cnt  = (float)(B_ * N_);
    float mean = d_bnsum[c] / cnt;
    float var  = d_bnsumsq[c] / cnt - mean * mean;
    float inv  = rsqrtf(var + 1e-5f);
    float g    = gamma[c] * inv;
    d_bnscale[c] = g;
    d_bnbias[c]  = beta[c] - mean * g;
}

__global__ void final_kernel(const float* __restrict__ x, float* __restrict__ out)
{
    int idx4 = blockIdx.x * blockDim.x + threadIdx.x;
    if (idx4 >= (B_ * C_ * N_) / 4) return;
    int idx = idx4 * 4;
    int c = (idx / N_) % C_;
    float sc = d_bnscale[c], bi = d_bnbias[c];
    float4 w  = *(const float4*)&d_wy[idx];
    float4 xv = *(const float4*)&x[idx];
    float4 o;
    o.x = fmaf(w.x, sc, bi) + xv.x;
    o.y = fmaf(w.y, sc, bi) + xv.y;
    o.z = fmaf(w.z, sc, bi) + xv.z;
    o.w = fmaf(w.w, sc, bi) + xv.w;
    *(float4*)&out[idx] = o;
}

// ---------------- launch ---------------------------------------------------------
extern "C" void kernel_launch(void* const* d_in, const int* in_sizes, int n_in,
                              void* d_out, int out_size)
{
    const float* x       = (const float*)d_in[0];
    const float* mp      = (const float*)d_in[1];
    const float* g_w     = (const float*)d_in[2];
    const float* g_b     = (const float*)d_in[3];
    const float* theta_w = (const float*)d_in[4];
    const float* theta_b = (const float*)d_in[5];
    const float* phi_w   = (const float*)d_in[6];
    const float* phi_b   = (const float*)d_in[7];
    const float* W_w     = (const float*)d_in[8];
    const float* W_b     = (const float*)d_in[9];
    const float* gamma   = (const float*)d_in[10];
    const float* beta    = (const float*)d_in[11];
    float* out = (float*)d_out;

    __nv_bfloat16 *xT_h, *xT_l, *mT_h, *mT_l, *pgw_h, *pgw_l, *tw_h, *tw_l;
    __nv_bfloat16 *Ww_h, *Ww_l, *ef_h, *y_h, *y_l;
    __half *thT, *phiP, *gsT, *Wp;
    float *pgN, *wy, *colsum, *pg_bias, *yF, *bnsum, *bnsumsq;
    cudaGetSymbolAddress((void**)&xT_h, d_xT_h);   cudaGetSymbolAddress((void**)&xT_l, d_xT_l);
    cudaGetSymbolAddress((void**)&mT_h, d_mT_h);   cudaGetSymbolAddress((void**)&mT_l, d_mT_l);
    cudaGetSymbolAddress((void**)&pgw_h, d_pgw_h); cudaGetSymbolAddress((void**)&pgw_l, d_pgw_l);
    cudaGetSymbolAddress((void**)&tw_h, d_tw_h);   cudaGetSymbolAddress((void**)&tw_l, d_tw_l);
    cudaGetSymbolAddress((void**)&Ww_h, d_Ww_h);   cudaGetSymbolAddress((void**)&Ww_l, d_Ww_l);
    cudaGetSymbolAddress((void**)&thT, d_thT);     cudaGetSymbolAddress((void**)&phiP, d_phiP);
    cudaGetSymbolAddress((void**)&gsT, d_gsT);     cudaGetSymbolAddress((void**)&Wp, d_W);
    cudaGetSymbolAddress((void**)&ef_h, d_ef_h);
    cudaGetSymbolAddress((void**)&y_h, d_y_h);     cudaGetSymbolAddress((void**)&y_l, d_y_l);
    cudaGetSymbolAddress((void**)&pgN, d_pgN);     cudaGetSymbolAddress((void**)&wy, d_wy);
    cudaGetSymbolAddress((void**)&colsum, d_colsum);
    cudaGetSymbolAddress((void**)&pg_bias, d_pg_bias);
    cudaGetSymbolAddress((void**)&yF, d_yF);
    cudaGetSymbolAddress((void**)&bnsum, d_bnsum);
    cudaGetSymbolAddress((void**)&bnsumsq, d_bnsumsq);

    cudaFuncSetAttribute((const void*)mma_gemm<0,0,0,0>, cudaFuncAttributeMaxDynamicSharedMemorySize, SMEM_TOT);
    cudaFuncSetAttribute((const void*)mma_gemm<5,0,0,0>, cudaFuncAttributeMaxDynamicSharedMemorySize, SMEM_TOT);
    cudaFuncSetAttribute((const void*)mma_gemm<2,1,1,1>, cudaFuncAttributeMaxDynamicSharedMemorySize, SMEM_TOT);
    cudaFuncSetAttribute((const void*)mma_gemm<3,1,1,1>, cudaFuncAttributeMaxDynamicSharedMemorySize, SMEM_TOT);
    cudaFuncSetAttribute((const void*)mma_gemm<4,0,0,0>, cudaFuncAttributeMaxDynamicSharedMemorySize, SMEM_TOT);

    // prep (launch idx 3 = theta-conv HMMA for ncu capture)
    split_weights<<<dim3(128, 4), 256>>>(g_w, theta_w, phi_w, W_w);          // 0
    stack_bias<<<1, 256>>>(phi_b, g_b);                                      // 1
    transpose_split<<<dim3(N_ / 32, C_ / 32, B_), dim3(32, 8)>>>(mp, mT_h, mT_l);  // 2
    // 3: theta conv -> single fp16 (z, N, CI)
    mma_gemm<5,0,0,0><<<dim3(1, N_ / 128, B_), 256, SMEM_TOT>>>(
        mT_h, mT_l, (size_t)N_ * C_, tw_h, tw_l, 0,
        N_, CI_, C_, 1, theta_b, nullptr,
        nullptr, (__nv_bfloat16*)thT, nullptr, (size_t)N_ * CI_, CI_, nullptr, nullptr, nullptr);
    transpose_split<<<dim3(N_ / 32, C_ / 32, B_), dim3(32, 8)>>>(x, xT_h, xT_l);   // 4
    // merged phi+g conv -> fp32 (z, N, 256)
    mma_gemm<0,0,0,0><<<dim3(2, N_ / 128, B_), 256, SMEM_TOT>>>(
        xT_h, xT_l, (size_t)N_ * C_, pgw_h, pgw_l, 0,
        N_, 2 * CI_, C_, 1, pg_bias, nullptr,
        pgN, nullptr, nullptr, (size_t)N_ * 2 * CI_, 2 * CI_, nullptr, nullptr, nullptr);
    cudaMemsetAsync(colsum, 0, B_ * NS_ * sizeof(float));
    cudaMemsetAsync(yF, 0, B_ * N_ * CI_ * sizeof(float));
    cudaMemsetAsync(bnsum, 0, C_ * sizeof(float));
    cudaMemsetAsync(bnsumsq, 0, C_ * sizeof(float));
    // pools
    pool_phi_k<<<dim3(NS_, B_), CI_>>>();
    pool_g_k<<<dim3(NS_, B_), CI_>>>();
    // g transposed to fp16 (unscaled — no colsum dependency)
    tr_convert_g<<<dim3(NS_ / 32, CI_ / 32, B_), dim3(32, 8)>>>();
    // f = exp(theta @ phi^T): fp16 single x single (1 product), colsum from quantized ef
    mma_gemm<2,1,1,1><<<dim3((NS_ + 127) / 128, N_ / 128, B_), 256, SMEM_TOT>>>(
        (const __nv_bfloat16*)thT, (const __nv_bfloat16*)thT, (size_t)N_ * CI_,
        (const __nv_bfloat16*)phiP, (const __nv_bfloat16*)phiP, (size_t)NS_ * CI_,
        N_, NS_, CI_, 1, nullptr, nullptr,
        nullptr, ef_h, nullptr, (size_t)N_ * NS_, NS_, colsum, nullptr, nullptr);
    // softmax weights W = ef / Z  (fp16)
    divide_W<<<(int)(((size_t)B_ * N_ * NS_ / 8 + 255) / 256), 256>>>();
    // y = W @ g^T: fp16 single x single (1 product), split-K=7, fp32 atomic accumulation
    mma_gemm<3,1,1,1><<<dim3(7, N_ / 128, B_), 256, SMEM_TOT>>>(
        (const __nv_bfloat16*)Wp, (const __nv_bfloat16*)Wp, (size_t)N_ * NS_,
        (const __nv_bfloat16*)gsT, (const __nv_bfloat16*)gsT, (size_t)CI_ * NS_,
        N_, CI_, NS_, 7, nullptr, nullptr,
        yF, nullptr, nullptr, (size_t)N_ * CI_, CI_, nullptr, nullptr, nullptr);
    // y -> split bf16
    y_convert<<<(B_ * N_ * CI_ / 2 + 255) / 256, 256>>>();
    // W_y = W_w @ y^T + W_b, fused BN stats
    mma_gemm<4,0,0,0><<<dim3(N_ / 128, C_ / 128, B_), 256, SMEM_TOT>>>(
        Ww_h, Ww_l, 0, y_h, y_l, (size_t)N_ * CI_,
        C_, N_, CI_, 1, nullptr, W_b,
        wy, nullptr, nullptr, (size_t)C_ * N_, N_, nullptr, bnsum, bnsumsq);
    // BN finalize + residual
    bn_finalize<<<1, 256>>>(gamma, beta);
    final_kernel<<<(B_ * C_ * N_ / 4 + 255) / 256, 256>>>(x, out);
}

// round 14
// speedup vs baseline: 1.1475x; 1.1475x over previous
#include <cuda_runtime.h>
#include <cuda_bf16.h>
#include <cuda_fp16.h>
#include <cstdint>

#define B_   2
#define C_   256
#define CI_  128
#define T_   16
#define H_   28
#define W_   28
#define N_   12544
#define HS_  14
#define WS_  14
#define NS_  3136

typedef unsigned long long u64;

// ---------------- scratch (device globals) -------------------------------------
__device__ __align__(16) __nv_bfloat16 d_xT_h[B_*N_*C_],  d_xT_l[B_*N_*C_];
__device__ __align__(16) __nv_bfloat16 d_mT_h[B_*N_*C_],  d_mT_l[B_*N_*C_];
__device__ __align__(16) __nv_bfloat16 d_pgw_h[2*CI_*C_], d_pgw_l[2*CI_*C_];
__device__ __align__(16) __nv_bfloat16 d_tw_h[CI_*C_],    d_tw_l[CI_*C_];
__device__ __align__(16) __nv_bfloat16 d_Ww_h[C_*CI_],    d_Ww_l[C_*CI_];
__device__ float d_pg_bias[2*CI_];
__device__ __align__(16) __half d_thT[B_*N_*CI_];                    // fp16 single
__device__ __align__(16) float d_pgN[B_*N_*2*CI_];
__device__ __align__(16) __half d_phiP[B_*NS_*CI_];                  // fp16 single
__device__ __align__(16) float d_gpool[B_*NS_*CI_];
__device__ __align__(16) __nv_bfloat16 d_gs_h[B_*CI_*NS_], d_gs_l[B_*CI_*NS_];  // g/Z split bf16
__device__ __align__(16) __nv_bfloat16 d_ef_h[(size_t)B_*N_*NS_];   // exp(f) bf16 (157 MB)
__device__ float d_colsum[B_*NS_];
__device__ __align__(16) float d_yF[B_*N_*CI_];
__device__ __align__(16) __nv_bfloat16 d_y_h[B_*N_*CI_], d_y_l[B_*N_*CI_];
__device__ __align__(16) float d_wy[B_*C_*N_];
__device__ float d_bnsum[C_], d_bnsumsq[C_];
__device__ float d_bnscale[C_], d_bnbias[C_];

// ---------------- PTX helpers ---------------------------------------------------
__device__ __forceinline__ uint32_t smem_u32(const void* p) {
    uint32_t a;
    asm("{ .reg .u64 t; cvta.to.shared.u64 t, %1; cvt.u32.u64 %0, t; }" : "=r"(a) : "l"(p));
    return a;
}
__device__ __forceinline__ void cpa16(uint32_t d, const void* s, int sz) {
    asm volatile("cp.async.ca.shared.global [%0], [%1], 16, %2;" :: "r"(d), "l"(s), "r"(sz));
}
__device__ __forceinline__ void cp_commit() { asm volatile("cp.async.commit_group;" ::: "memory"); }
template <int Ngrp>
__device__ __forceinline__ void cp_waitN() {
    asm volatile("cp.async.wait_group %0;" :: "n"(Ngrp) : "memory");
}

__device__ __forceinline__ void ldm4(uint32_t* r, uint32_t a) {
    asm volatile("ldmatrix.sync.aligned.m8n8.x4.shared.b16 {%0,%1,%2,%3}, [%4];"
                 : "=r"(r[0]), "=r"(r[1]), "=r"(r[2]), "=r"(r[3]) : "r"(a));
}
__device__ __forceinline__ void mma_bf16(float* c, const uint32_t* a, uint32_t b0, uint32_t b1) {
    asm volatile("mma.sync.aligned.m16n8k16.row.col.f32.bf16.bf16.f32 "
                 "{%0,%1,%2,%3}, {%4,%5,%6,%7}, {%8,%9}, {%0,%1,%2,%3};"
                 : "+f"(c[0]), "+f"(c[1]), "+f"(c[2]), "+f"(c[3])
                 : "r"(a[0]), "r"(a[1]), "r"(a[2]), "r"(a[3]), "r"(b0), "r"(b1));
}
__device__ __forceinline__ void mma_fp16(float* c, const uint32_t* a, uint32_t b0, uint32_t b1) {
    asm volatile("mma.sync.aligned.m16n8k16.row.col.f32.f16.f16.f32 "
                 "{%0,%1,%2,%3}, {%4,%5,%6,%7}, {%8,%9}, {%0,%1,%2,%3};"
                 : "+f"(c[0]), "+f"(c[1]), "+f"(c[2]), "+f"(c[3])
                 : "r"(a[0]), "r"(a[1]), "r"(a[2]), "r"(a[3]), "r"(b0), "r"(b1));
}
__device__ __forceinline__ void store_split2(__nv_bfloat16* hi, __nv_bfloat16* lo,
                                             size_t o, float v0, float v1) {
    __nv_bfloat16 h0 = __float2bfloat16(v0), h1 = __float2bfloat16(v1);
    __nv_bfloat162 hv; hv.x = h0; hv.y = h1;
    __nv_bfloat162 lv;
    lv.x = __float2bfloat16(v0 - __bfloat162float(h0));
    lv.y = __float2bfloat16(v1 - __bfloat162float(h1));
    *(__nv_bfloat162*)(hi + o) = hv;
    *(__nv_bfloat162*)(lo + o) = lv;
}

// ---------------- generic split-bf16/fp16 HMMA GEMM ------------------------------
// AS: A single   BS: B single   HALF: fp16 MMA for Ah*Bh   STAGES: pipeline depth
// Compact smem staging: tiles per stage = 2 + !AS + !BS (AH[,AL],BH[,BL])
// EPI 0: fp32 store (+biasCol/+biasRow)
// EPI 2: exp -> bf16 quantize -> colsum atomics (from quantized) + staged bf16 store
// EPI 3: fp32 atomicAdd (split-K partials)
// EPI 4: fp32 store (+biasRow) + per-channel sum/sumsq atomics (fused BN stats)
// EPI 5: single-fp16 store (+biasCol)
#define TROW 80
#define TILE_BYTES (128*TROW)
#define EROW 136

template <int AS, int BS>
__device__ __forceinline__ void copy_chunk(uint32_t base,
    const __nv_bfloat16* Ah, const __nv_bfloat16* Al, int i0,
    const __nv_bfloat16* Bh, const __nv_bfloat16* Bl, int j0, int Nn,
    int K, int k0, int tid)
{
    constexpr uint32_t O_AH = 0;
    constexpr uint32_t O_AL = TILE_BYTES;                       // valid iff !AS
    constexpr uint32_t O_BH = (AS ? 1u : 2u) * TILE_BYTES;
    constexpr uint32_t O_BL = O_BH + TILE_BYTES;                // valid iff !BS
#pragma unroll
    for (int i = 0; i < 2; i++) {
        int e = tid + i * 256;
        int r = e >> 2, seg = e & 3;
        uint32_t doff = r * TROW + seg * 16;
        size_t asrc = (size_t)(i0 + r) * K + k0 + seg * 8;
        cpa16(base + O_AH + doff, Ah + asrc, 16);
        if (!AS) cpa16(base + O_AL + doff, Al + asrc, 16);
        int brow = j0 + r;
        int sz = (brow < Nn) ? 16 : 0;
        int brc = (brow < Nn) ? brow : (Nn - 1);
        size_t bsrc = (size_t)brc * K + k0 + seg * 8;
        cpa16(base + O_BH + doff, Bh + bsrc, sz);
        if (!BS) cpa16(base + O_BL + doff, Bl + bsrc, sz);
    }
}

template <int EPI, int AS, int BS, int HALF, int STAGES>
__global__ void __launch_bounds__(256, 2)
mma_gemm(const __nv_bfloat16* __restrict__ Ah, const __nv_bfloat16* __restrict__ Al, size_t strA,
         const __nv_bfloat16* __restrict__ Bh, const __nv_bfloat16* __restrict__ Bl, size_t strB,
         int M, int Nn, int K, int ksplits,
         const float* __restrict__ biasCol, const float* __restrict__ biasRow,
         float* __restrict__ outF,
         __nv_bfloat16* __restrict__ outHi, __nv_bfloat16* __restrict__ outLo,
         size_t strO, int ldO,
         float* __restrict__ colsum,
         float* __restrict__ bnsum, float* __restrict__ bnsumsq)
{
    extern __shared__ __align__(128) char smem[];
    constexpr int NT = 2 + (AS ? 0 : 1) + (BS ? 0 : 1);
    constexpr uint32_t ST_BYTES = (uint32_t)NT * TILE_BYTES;
    constexpr uint32_t O_AH = 0;
    constexpr uint32_t O_AL = TILE_BYTES;
    constexpr uint32_t O_BH = (AS ? 1u : 2u) * TILE_BYTES;
    constexpr uint32_t O_BL = O_BH + TILE_BYTES;

    const uint32_t sb = smem_u32(smem);
    const int tid = threadIdx.x, lane = tid & 31, wid = tid >> 5;
    const int wm = wid >> 2, wn = wid & 3;
    const int z  = blockIdx.z;
    const int ksid = blockIdx.x % ksplits;
    const int i0 = blockIdx.y * 128, j0 = (blockIdx.x / ksplits) * 128;
    const int kLen = K / ksplits;      // must be a multiple of 32
    const int kOff = ksid * kLen;

    const __nv_bfloat16* Ahz = Ah + (size_t)z * strA;
    const __nv_bfloat16* Alz = Al + (size_t)z * strA;
    const __nv_bfloat16* Bhz = Bh + (size_t)z * strB;
    const __nv_bfloat16* Blz = Bl + (size_t)z * strB;

    float acc[4][4][4];
#pragma unroll
    for (int a = 0; a < 4; a++)
#pragma unroll
        for (int b = 0; b < 4; b++)
#pragma unroll
            for (int c = 0; c < 4; c++) acc[a][b][c] = 0.f;

    const uint32_t aBase = sb + (uint32_t)((wm * 64 + (lane & 15)) * TROW + (lane >> 4) * 16);
    const uint32_t bBase = sb + (uint32_t)((wn * 32 + (lane & 7) + ((lane & 16) ? 8 : 0)) * TROW
                                           + ((lane & 8) ? 16 : 0));

    const int nch = kLen / 32;
    // prologue: fill STAGES-1 stages
#pragma unroll
    for (int p = 0; p < STAGES - 1; p++) {
        if (p < nch) {
            copy_chunk<AS, BS>(sb + (uint32_t)p * ST_BYTES, Ahz, Alz, i0, Bhz, Blz,
                               j0, Nn, K, kOff + p * 32, tid);
            cp_commit();
        }
    }
    for (int ch = 0; ch < nch; ch++) {
        cp_waitN<STAGES - 2>();
        __syncthreads();
        int nxt = ch + STAGES - 1;
        if (nxt < nch) {
            copy_chunk<AS, BS>(sb + (uint32_t)(nxt % STAGES) * ST_BYTES, Ahz, Alz, i0,
                               Bhz, Blz, j0, Nn, K, kOff + nxt * 32, tid);
            cp_commit();
        }
        const uint32_t buf = (uint32_t)(ch % STAGES) * ST_BYTES;
#pragma unroll
        for (int ks = 0; ks < 2; ks++) {
            uint32_t bh[8], bl[8];
#pragma unroll
            for (int grp = 0; grp < 2; grp++) {
                ldm4(&bh[grp * 4], bBase + buf + O_BH + grp * (16 * TROW) + ks * 32);
                if (!BS)
                    ldm4(&bl[grp * 4], bBase + buf + O_BL + grp * (16 * TROW) + ks * 32);
            }
#pragma unroll
            for (int am = 0; am < 4; am++) {
                uint32_t ah4[4], al4[4];
                ldm4(ah4, aBase + buf + O_AH + am * (16 * TROW) + ks * 32);
                if (!AS)
                    ldm4(al4, aBase + buf + O_AL + am * (16 * TROW) + ks * 32);
#pragma unroll
                for (int bn = 0; bn < 4; bn++) {
                    if (HALF) mma_fp16(acc[am][bn], ah4, bh[bn * 2], bh[bn * 2 + 1]);
                    else      mma_bf16(acc[am][bn], ah4, bh[bn * 2], bh[bn * 2 + 1]);
                }
                if (!BS) {
#pragma unroll
                    for (int bn = 0; bn < 4; bn++)
                        mma_bf16(acc[am][bn], ah4, bl[bn * 2], bl[bn * 2 + 1]);
                }
                if (!AS) {
#pragma unroll
                    for (int bn = 0; bn < 4; bn++)
                        mma_bf16(acc[am][bn], al4, bh[bn * 2], bh[bn * 2 + 1]);
                }
            }
        }
    }

    // ---- epilogue ----
    const int q    = lane >> 2;
    const int rloc = wm * 64 + q;
    const int cloc = wn * 32 + (lane & 3) * 2;

    if (EPI == 2) {
        __syncthreads();
        __nv_bfloat16* sh = (__nv_bfloat16*)smem;                       // [128][EROW]
        float cs[4][2];
#pragma unroll
        for (int bn = 0; bn < 4; bn++) { cs[bn][0] = 0.f; cs[bn][1] = 0.f; }
#pragma unroll
        for (int am = 0; am < 4; am++) {
            int rl = rloc + am * 16;
#pragma unroll
            for (int bn = 0; bn < 4; bn++) {
                int jl = cloc + bn * 8;
                __nv_bfloat16 h0 = __float2bfloat16(__expf(acc[am][bn][0]));
                __nv_bfloat16 h1 = __float2bfloat16(__expf(acc[am][bn][1]));
                __nv_bfloat16 h2 = __float2bfloat16(__expf(acc[am][bn][2]));
                __nv_bfloat16 h3 = __float2bfloat16(__expf(acc[am][bn][3]));
                cs[bn][0] += __bfloat162float(h0) + __bfloat162float(h2);
                cs[bn][1] += __bfloat162float(h1) + __bfloat162float(h3);
                __nv_bfloat162 hv01; hv01.x = h0; hv01.y = h1;
                __nv_bfloat162 hv23; hv23.x = h2; hv23.y = h3;
                *(__nv_bfloat162*)&sh[rl * EROW + jl]       = hv01;
                *(__nv_bfloat162*)&sh[(rl + 8) * EROW + jl] = hv23;
            }
        }
#pragma unroll
        for (int bn = 0; bn < 4; bn++)
#pragma unroll
            for (int jj = 0; jj < 2; jj++) {
                float v = cs[bn][jj];
                v += __shfl_xor_sync(0xffffffffu, v, 4);
                v += __shfl_xor_sync(0xffffffffu, v, 8);
                v += __shfl_xor_sync(0xffffffffu, v, 16);
                if (q == 0) {
                    int jg = j0 + cloc + bn * 8 + jj;
                    if (jg < Nn) atomicAdd(&colsum[z * Nn + jg], v);
                }
            }
        __syncthreads();
#pragma unroll
        for (int it = 0; it < 8; it++) {
            int e = it * 256 + tid;
            int r = e >> 4, s = e & 15;
            int jg = j0 + s * 8;
            if (jg < Nn) {
                size_t o = (size_t)z * strO + (size_t)(i0 + r) * ldO + jg;
                *(uint4*)(outHi + o) = *(const uint4*)&sh[r * EROW + s * 8];
            }
        }
    } else if (EPI == 5) {
        __half* outH = (__half*)outHi;
#pragma unroll
        for (int am = 0; am < 4; am++) {
            int ig0 = i0 + rloc + am * 16;
#pragma unroll
            for (int bn = 0; bn < 4; bn++) {
                int jg = j0 + cloc + bn * 8;
                if (jg < Nn) {
                    float bc0 = biasCol ? biasCol[jg]     : 0.f;
                    float bc1 = biasCol ? biasCol[jg + 1] : 0.f;
                    size_t o0 = (size_t)z * strO + (size_t)ig0 * ldO + jg;
                    __half2 v01; v01.x = __float2half(acc[am][bn][0] + bc0);
                                 v01.y = __float2half(acc[am][bn][1] + bc1);
                    __half2 v23; v23.x = __float2half(acc[am][bn][2] + bc0);
                                 v23.y = __float2half(acc[am][bn][3] + bc1);
                    *(__half2*)(outH + o0) = v01;
                    *(__half2*)(outH + o0 + (size_t)8 * ldO) = v23;
                }
            }
        }
    } else if (EPI == 3) {
#pragma unroll
        for (int am = 0; am < 4; am++) {
            int ig0 = i0 + rloc + am * 16;
#pragma unroll
            for (int bn = 0; bn < 4; bn++) {
                int jg = j0 + cloc + bn * 8;
                if (jg < Nn) {
                    size_t o0 = (size_t)z * strO + (size_t)ig0 * ldO + jg;
                    atomicAdd(outF + o0,     acc[am][bn][0]);
                    atomicAdd(outF + o0 + 1, acc[am][bn][1]);
                    atomicAdd(outF + o0 + (size_t)8 * ldO,     acc[am][bn][2]);
                    atomicAdd(outF + o0 + (size_t)8 * ldO + 1, acc[am][bn][3]);
                }
            }
        }
    } else {  // EPI 0 / 4
#pragma unroll
        for (int am = 0; am < 4; am++) {
            int ig0 = i0 + rloc + am * 16;
            float br0 = biasRow ? biasRow[ig0]     : 0.f;
            float br1 = biasRow ? biasRow[ig0 + 8] : 0.f;
            float sA = 0.f, sqA = 0.f, sB = 0.f, sqB = 0.f;
#pragma unroll
            for (int bn = 0; bn < 4; bn++) {
                int jg = j0 + cloc + bn * 8;
                if (jg < Nn) {
                    float bc0 = biasCol ? biasCol[jg]     : 0.f;
                    float bc1 = biasCol ? biasCol[jg + 1] : 0.f;
                    float v0 = acc[am][bn][0] + bc0 + br0;
                    float v1 = acc[am][bn][1] + bc1 + br0;
                    float v2 = acc[am][bn][2] + bc0 + br1;
                    float v3 = acc[am][bn][3] + bc1 + br1;
                    size_t o0 = (size_t)z * strO + (size_t)ig0 * ldO + jg;
                    *(float2*)(outF + o0) = make_float2(v0, v1);
                    *(float2*)(outF + o0 + (size_t)8 * ldO) = make_float2(v2, v3);
                    if (EPI == 4) {
                        sA += v0 + v1;  sqA += v0 * v0 + v1 * v1;
                        sB += v2 + v3;  sqB += v2 * v2 + v3 * v3;
                    }
                }
            }
            if (EPI == 4) {
                sA  += __shfl_xor_sync(0xffffffffu, sA, 1);
                sA  += __shfl_xor_sync(0xffffffffu, sA, 2);
                sqA += __shfl_xor_sync(0xffffffffu, sqA, 1);
                sqA += __shfl_xor_sync(0xffffffffu, sqA, 2);
                sB  += __shfl_xor_sync(0xffffffffu, sB, 1);
                sB  += __shfl_xor_sync(0xffffffffu, sB, 2);
                sqB += __shfl_xor_sync(0xffffffffu, sqB, 1);
                sqB += __shfl_xor_sync(0xffffffffu, sqB, 2);
                if ((lane & 3) == 0) {
                    atomicAdd(&bnsum[ig0],       sA);
                    atomicAdd(&bnsumsq[ig0],     sqA);
                    atomicAdd(&bnsum[ig0 + 8],   sB);
                    atomicAdd(&bnsumsq[ig0 + 8], sqB);
                }
            }
        }
    }
}

// ---------------- prep / pool / BN kernels --------------------------------------
__global__ void split_weights(const float* __restrict__ g_w, const float* __restrict__ t_w,
                              const float* __restrict__ p_w, const float* __restrict__ W_w)
{
    int i = blockIdx.x * 256 + threadIdx.x;
    int which = blockIdx.y;
    const float* in = (which == 0) ? g_w : (which == 1) ? t_w : (which == 2) ? p_w : W_w;
    __nv_bfloat16* ho = (which == 0) ? (d_pgw_h + CI_ * C_) : (which == 1) ? d_tw_h
                      : (which == 2) ? d_pgw_h : d_Ww_h;
    __nv_bfloat16* lo = (which == 0) ? (d_pgw_l + CI_ * C_) : (which == 1) ? d_tw_l
                      : (which == 2) ? d_pgw_l : d_Ww_l;
    float v = in[i];
    __nv_bfloat16 h = __float2bfloat16(v);
    ho[i] = h;
    lo[i] = __float2bfloat16(v - __bfloat162float(h));
}

__global__ void stack_bias(const float* __restrict__ phi_b, const float* __restrict__ g_b)
{
    int i = threadIdx.x;
    d_pg_bias[i] = (i < CI_) ? phi_b[i] : g_b[i - CI_];
}

__global__ void transpose_split(const float* __restrict__ in,
                                __nv_bfloat16* __restrict__ hi, __nv_bfloat16* __restrict__ lo)
{
    __shared__ float t[32][33];
    int z  = blockIdx.z;
    int n0 = blockIdx.x * 32, c0 = blockIdx.y * 32;
    int tx = threadIdx.x, ty = threadIdx.y;
    const float* ip = in + (size_t)z * C_ * N_;
#pragma unroll
    for (int i = 0; i < 4; i++)
        t[ty + 8 * i][tx] = ip[(size_t)(c0 + ty + 8 * i) * N_ + n0 + tx];
    __syncthreads();
#pragma unroll
    for (int i = 0; i < 4; i++) {
        float v = t[tx][ty + 8 * i];
        __nv_bfloat16 h = __float2bfloat16(v);
        size_t o = ((size_t)z * N_ + n0 + ty + 8 * i) * C_ + c0 + tx;
        hi[o] = h;
        lo[o] = __float2bfloat16(v - __bfloat162float(h));
    }
}

// phi: pooled -> single fp16 (z, NS, CI)
__global__ void pool_phi_k()
{
    int m = blockIdx.x, z = blockIdx.y, ci = threadIdx.x;
    int t  = m / (HS_ * WS_);
    int r  = m % (HS_ * WS_);
    int h2 = r / WS_, w2 = r % WS_;
    int n00 = t * (H_ * W_) + 2 * h2 * W_ + 2 * w2;
    const float* p = d_pgN + (size_t)z * N_ * 2 * CI_ + ci;
    const int ld = 2 * CI_;
    float v = fmaxf(fmaxf(p[(size_t)n00 * ld],        p[(size_t)(n00 + 1) * ld]),
                    fmaxf(p[(size_t)(n00 + W_) * ld], p[(size_t)(n00 + W_ + 1) * ld]));
    d_phiP[((size_t)z * NS_ + m) * CI_ + ci] = __float2half(v);
}

__global__ void pool_g_k()
{
    int m = blockIdx.x, z = blockIdx.y, ci = threadIdx.x;
    int t  = m / (HS_ * WS_);
    int r  = m % (HS_ * WS_);
    int h2 = r / WS_, w2 = r % WS_;
    int n00 = t * (H_ * W_) + 2 * h2 * W_ + 2 * w2;
    const float* p = d_pgN + (size_t)z * N_ * 2 * CI_ + CI_ + ci;
    const int ld = 2 * CI_;
    float v = fmaxf(fmaxf(p[(size_t)n00 * ld],        p[(size_t)(n00 + 1) * ld]),
                    fmaxf(p[(size_t)(n00 + W_) * ld], p[(size_t)(n00 + W_ + 1) * ld]));
    d_gpool[((size_t)z * NS_ + m) * CI_ + ci] = v;
}

// gpool (z, NS, CI) fp32 / colsum -> gs (z, CI, NS) bf16 hi/lo
__global__ void scale_tr_split_g()
{
    __shared__ float t[32][33];
    int z  = blockIdx.z;
    int m0 = blockIdx.x * 32, c0 = blockIdx.y * 32;
    int tx = threadIdx.x, ty = threadIdx.y;
#pragma unroll
    for (int i = 0; i < 4; i++)
        t[ty + 8 * i][tx] = d_gpool[((size_t)z * NS_ + m0 + ty + 8 * i) * CI_ + c0 + tx];
    __syncthreads();
    float inv = 1.0f / d_colsum[z * NS_ + m0 + tx];
#pragma unroll
    for (int i = 0; i < 4; i++) {
        float v = t[tx][ty + 8 * i] * inv;
        __nv_bfloat16 h = __float2bfloat16(v);
        size_t o = ((size_t)z * CI_ + c0 + ty + 8 * i) * NS_ + m0 + tx;
        d_gs_h[o] = h;
        d_gs_l[o] = __float2bfloat16(v - __bfloat162float(h));
    }
}

// y fp32 -> split bf16
__global__ void y_convert()
{
    int i2 = blockIdx.x * 256 + threadIdx.x;
    if (i2 >= B_ * N_ * CI_ / 2) return;
    float2 v = *(const float2*)&d_yF[i2 * 2];
    store_split2(d_y_h, d_y_l, (size_t)i2 * 2, v.x, v.y);
}

__global__ void bn_finalize(const float* __restrict__ gamma, const float* __restrict__ beta)
{
    int c = threadIdx.x;
    float cnt  = (float)(B_ * N_);
    float mean = d_bnsum[c] / cnt;
    float var  = d_bnsumsq[c] / cnt - mean * mean;
    float inv  = rsqrtf(var + 1e-5f);
    float g    = gamma[c] * inv;
    d_bnscale[c] = g;
    d_bnbias[c]  = beta[c] - mean * g;
}

__global__ void final_kernel(const float* __restrict__ x, float* __restrict__ out)
{
    int idx4 = blockIdx.x * blockDim.x + threadIdx.x;
    if (idx4 >= (B_ * C_ * N_) / 4) return;
    int idx = idx4 * 4;
    int c = (idx / N_) % C_;
    float sc = d_bnscale[c], bi = d_bnbias[c];
    float4 w  = *(const float4*)&d_wy[idx];
    float4 xv = *(const float4*)&x[idx];
    float4 o;
    o.x = fmaf(w.x, sc, bi) + xv.x;
    o.y = fmaf(w.y, sc, bi) + xv.y;
    o.z = fmaf(w.z, sc, bi) + xv.z;
    o.w = fmaf(w.w, sc, bi) + xv.w;
    *(float4*)&out[idx] = o;
}

// ---------------- launch ---------------------------------------------------------
extern "C" void kernel_launch(void* const* d_in, const int* in_sizes, int n_in,
                              void* d_out, int out_size)
{
    const float* x       = (const float*)d_in[0];
    const float* mp      = (const float*)d_in[1];
    const float* g_w     = (const float*)d_in[2];
    const float* g_b     = (const float*)d_in[3];
    const float* theta_w = (const float*)d_in[4];
    const float* theta_b = (const float*)d_in[5];
    const float* phi_w   = (const float*)d_in[6];
    const float* phi_b   = (const float*)d_in[7];
    const float* W_w     = (const float*)d_in[8];
    const float* W_b     = (const float*)d_in[9];
    const float* gamma   = (const float*)d_in[10];
    const float* beta    = (const float*)d_in[11];
    float* out = (float*)d_out;

    __nv_bfloat16 *xT_h, *xT_l, *mT_h, *mT_l, *pgw_h, *pgw_l, *tw_h, *tw_l;
    __nv_bfloat16 *Ww_h, *Ww_l, *gs_h, *gs_l, *ef_h, *y_h, *y_l;
    __half *thT, *phiP;
    float *pgN, *wy, *colsum, *pg_bias, *yF, *bnsum, *bnsumsq;
    cudaGetSymbolAddress((void**)&xT_h, d_xT_h);   cudaGetSymbolAddress((void**)&xT_l, d_xT_l);
    cudaGetSymbolAddress((void**)&mT_h, d_mT_h);   cudaGetSymbolAddress((void**)&mT_l, d_mT_l);
    cudaGetSymbolAddress((void**)&pgw_h, d_pgw_h); cudaGetSymbolAddress((void**)&pgw_l, d_pgw_l);
    cudaGetSymbolAddress((void**)&tw_h, d_tw_h);   cudaGetSymbolAddress((void**)&tw_l, d_tw_l);
    cudaGetSymbolAddress((void**)&Ww_h, d_Ww_h);   cudaGetSymbolAddress((void**)&Ww_l, d_Ww_l);
    cudaGetSymbolAddress((void**)&thT, d_thT);     cudaGetSymbolAddress((void**)&phiP, d_phiP);
    cudaGetSymbolAddress((void**)&gs_h, d_gs_h);   cudaGetSymbolAddress((void**)&gs_l, d_gs_l);
    cudaGetSymbolAddress((void**)&ef_h, d_ef_h);
    cudaGetSymbolAddress((void**)&y_h, d_y_h);     cudaGetSymbolAddress((void**)&y_l, d_y_l);
    cudaGetSymbolAddress((void**)&pgN, d_pgN);     cudaGetSymbolAddress((void**)&wy, d_wy);
    cudaGetSymbolAddress((void**)&colsum, d_colsum);
    cudaGetSymbolAddress((void**)&pg_bias, d_pg_bias);
    cudaGetSymbolAddress((void**)&yF, d_yF);
    cudaGetSymbolAddress((void**)&bnsum, d_bnsum);
    cudaGetSymbolAddress((void**)&bnsumsq, d_bnsumsq);

    // smem sizes: tiles/stage * stages * TILE_BYTES
    const int SM_CONV = 2 * 4 * TILE_BYTES;    // 81920: AS=0,BS=0, 2 stages
    const int SM_F    = 4 * 2 * TILE_BYTES;    // 81920: AS=1,BS=1, 4 stages
    const int SM_Y    = 3 * 3 * TILE_BYTES;    // 92160: AS=1,BS=0, 3 stages
    cudaFuncSetAttribute((const void*)mma_gemm<0,0,0,0,2>, cudaFuncAttributeMaxDynamicSharedMemorySize, SM_CONV);
    cudaFuncSetAttribute((const void*)mma_gemm<5,0,0,0,2>, cudaFuncAttributeMaxDynamicSharedMemorySize, SM_CONV);
    cudaFuncSetAttribute((const void*)mma_gemm<2,1,1,1,4>, cudaFuncAttributeMaxDynamicSharedMemorySize, SM_F);
    cudaFuncSetAttribute((const void*)mma_gemm<3,1,0,0,3>, cudaFuncAttributeMaxDynamicSharedMemorySize, SM_Y);
    cudaFuncSetAttribute((const void*)mma_gemm<4,0,0,0,2>, cudaFuncAttributeMaxDynamicSharedMemorySize, SM_CONV);

    // prep (launch idx 3 = theta-conv HMMA for ncu capture)
    split_weights<<<dim3(128, 4), 256>>>(g_w, theta_w, phi_w, W_w);          // 0
    stack_bias<<<1, 256>>>(phi_b, g_b);                                      // 1
    transpose_split<<<dim3(N_ / 32, C_ / 32, B_), dim3(32, 8)>>>(mp, mT_h, mT_l);  // 2
    // 3: theta conv -> single fp16 (z, N, CI)
    mma_gemm<5,0,0,0,2><<<dim3(1, N_ / 128, B_), 256, SM_CONV>>>(
        mT_h, mT_l, (size_t)N_ * C_, tw_h, tw_l, 0,
        N_, CI_, C_, 1, theta_b, nullptr,
        nullptr, (__nv_bfloat16*)thT, nullptr, (size_t)N_ * CI_, CI_, nullptr, nullptr, nullptr);
    transpose_split<<<dim3(N_ / 32, C_ / 32, B_), dim3(32, 8)>>>(x, xT_h, xT_l);   // 4
    // merged phi+g conv -> fp32 (z, N, 256)
    mma_gemm<0,0,0,0,2><<<dim3(2, N_ / 128, B_), 256, SM_CONV>>>(
        xT_h, xT_l, (size_t)N_ * C_, pgw_h, pgw_l, 0,
        N_, 2 * CI_, C_, 1, pg_bias, nullptr,
        pgN, nullptr, nullptr, (size_t)N_ * 2 * CI_, 2 * CI_, nullptr, nullptr, nullptr);
    cudaMemsetAsync(colsum, 0, B_ * NS_ * sizeof(float));
    cudaMemsetAsync(yF, 0, B_ * N_ * CI_ * sizeof(float));
    cudaMemsetAsync(bnsum, 0, C_ * sizeof(float));
    cudaMemsetAsync(bnsumsq, 0, C_ * sizeof(float));
    // pools
    pool_phi_k<<<dim3(NS_, B_), CI_>>>();
    pool_g_k<<<dim3(NS_, B_), CI_>>>();
    // f = exp(theta @ phi^T): fp16 single x single, 4-stage pipeline
    mma_gemm<2,1,1,1,4><<<dim3((NS_ + 127) / 128, N_ / 128, B_), 256, SM_F>>>(
        (const __nv_bfloat16*)thT, (const __nv_bfloat16*)thT, (size_t)N_ * CI_,
        (const __nv_bfloat16*)phiP, (const __nv_bfloat16*)phiP, (size_t)NS_ * CI_,
        N_, NS_, CI_, 1, nullptr, nullptr,
        nullptr, ef_h, nullptr, (size_t)N_ * NS_, NS_, colsum, nullptr, nullptr);
    // g scaled by 1/Z, transposed, split bf16
    scale_tr_split_g<<<dim3(NS_ / 32, CI_ / 32, B_), dim3(32, 8)>>>();
    // y = ef @ gs^T: A single bf16 (2 products), 3-stage pipeline, split-K=7
    mma_gemm<3,1,0,0,3><<<dim3(7, N_ / 128, B_), 256, SM_Y>>>(
        ef_h, ef_h, (size_t)N_ * NS_, gs_h, gs_l, (size_t)CI_ * NS_,
        N_, CI_, NS_, 7, nullptr, nullptr,
        yF, nullptr, nullptr, (size_t)N_ * CI_, CI_, nullptr, nullptr, nullptr);
    // y -> split bf16
    y_convert<<<(B_ * N_ * CI_ / 2 + 255) / 256, 256>>>();
    // W_y = W_w @ y^T + W_b, fused BN stats
    mma_gemm<4,0,0,0,2><<<dim3(N_ / 128, C_ / 128, B_), 256, SM_CONV>>>(
        Ww_h, Ww_l, 0, y_h, y_l, (size_t)N_ * CI_,
        C_, N_, CI_, 1, nullptr, W_b,
        wy, nullptr, nullptr, (size_t)C_ * N_, N_, nullptr, bnsum, bnsumsq);
    // BN finalize + residual
    bn_finalize<<<1, 256>>>(gamma, beta);
    final_kernel<<<(B_ * C_ * N_ / 4 + 255) / 256, 256>>>(x, out);
}

// round 15
// speedup vs baseline: 1.2007x; 1.0464x over previous
#include <cuda_runtime.h>
#include <cuda_bf16.h>
#include <cuda_fp16.h>
#include <cstdint>

#define B_   2
#define C_   256
#define CI_  128
#define T_   16
#define H_   28
#define W_   28
#define N_   12544
#define HS_  14
#define WS_  14
#define NS_  3136
#define CW_  (3*CI_)     // stacked conv output channels: [phi | g | theta]

typedef unsigned long long u64;

// ---------------- scratch (device globals) -------------------------------------
__device__ __align__(16) __nv_bfloat16 d_xT_h[B_*N_*C_],  d_xT_l[B_*N_*C_];
__device__ __align__(16) __nv_bfloat16 d_mT_h[B_*N_*C_],  d_mT_l[B_*N_*C_];
__device__ __align__(16) __nv_bfloat16 d_cw_h[CW_*C_],    d_cw_l[CW_*C_];   // stacked phi/g/theta weights
__device__ __align__(16) __nv_bfloat16 d_Ww_h[C_*CI_],    d_Ww_l[C_*CI_];
__device__ float d_c_bias[CW_];
__device__ __align__(16) float d_convN[B_*N_*CW_];        // (z, N, 384) fp32 conv outputs
__device__ __align__(16) __half d_thT[B_*N_*CI_];         // theta fp16 single
__device__ __align__(16) __half d_phiP[B_*NS_*CI_];       // phi pooled fp16 single
__device__ __align__(16) float d_gpool[B_*NS_*CI_];
__device__ __align__(16) __nv_bfloat16 d_gs_h[B_*CI_*NS_], d_gs_l[B_*CI_*NS_];  // g/Z split bf16
__device__ __align__(16) __nv_bfloat16 d_ef_h[(size_t)B_*N_*NS_];   // exp(f) bf16 (157 MB)
__device__ float d_colsum[B_*NS_];
__device__ __align__(16) float d_yF[B_*N_*CI_];
__device__ __align__(16) __nv_bfloat16 d_y_h[B_*N_*CI_], d_y_l[B_*N_*CI_];
__device__ __align__(16) float d_wy[B_*C_*N_];
__device__ float d_bnsum[C_], d_bnsumsq[C_];
__device__ float d_bnscale[C_], d_bnbias[C_];

// ---------------- PTX helpers ---------------------------------------------------
__device__ __forceinline__ uint32_t smem_u32(const void* p) {
    uint32_t a;
    asm("{ .reg .u64 t; cvta.to.shared.u64 t, %1; cvt.u32.u64 %0, t; }" : "=r"(a) : "l"(p));
    return a;
}
__device__ __forceinline__ void cpa16(uint32_t d, const void* s, int sz) {
    asm volatile("cp.async.ca.shared.global [%0], [%1], 16, %2;" :: "r"(d), "l"(s), "r"(sz));
}
__device__ __forceinline__ void cp_commit() { asm volatile("cp.async.commit_group;" ::: "memory"); }
__device__ __forceinline__ void cp_wait0()  { asm volatile("cp.async.wait_group 0;"  ::: "memory"); }

__device__ __forceinline__ void ldm4(uint32_t* r, uint32_t a) {
    asm volatile("ldmatrix.sync.aligned.m8n8.x4.shared.b16 {%0,%1,%2,%3}, [%4];"
                 : "=r"(r[0]), "=r"(r[1]), "=r"(r[2]), "=r"(r[3]) : "r"(a));
}
__device__ __forceinline__ void mma_bf16(float* c, const uint32_t* a, uint32_t b0, uint32_t b1) {
    asm volatile("mma.sync.aligned.m16n8k16.row.col.f32.bf16.bf16.f32 "
                 "{%0,%1,%2,%3}, {%4,%5,%6,%7}, {%8,%9}, {%0,%1,%2,%3};"
                 : "+f"(c[0]), "+f"(c[1]), "+f"(c[2]), "+f"(c[3])
                 : "r"(a[0]), "r"(a[1]), "r"(a[2]), "r"(a[3]), "r"(b0), "r"(b1));
}
__device__ __forceinline__ void mma_fp16(float* c, const uint32_t* a, uint32_t b0, uint32_t b1) {
    asm volatile("mma.sync.aligned.m16n8k16.row.col.f32.f16.f16.f32 "
                 "{%0,%1,%2,%3}, {%4,%5,%6,%7}, {%8,%9}, {%0,%1,%2,%3};"
                 : "+f"(c[0]), "+f"(c[1]), "+f"(c[2]), "+f"(c[3])
                 : "r"(a[0]), "r"(a[1]), "r"(a[2]), "r"(a[3]), "r"(b0), "r"(b1));
}
__device__ __forceinline__ void store_split2(__nv_bfloat16* hi, __nv_bfloat16* lo,
                                             size_t o, float v0, float v1) {
    __nv_bfloat16 h0 = __float2bfloat16(v0), h1 = __float2bfloat16(v1);
    __nv_bfloat162 hv; hv.x = h0; hv.y = h1;
    __nv_bfloat162 lv;
    lv.x = __float2bfloat16(v0 - __bfloat162float(h0));
    lv.y = __float2bfloat16(v1 - __bfloat162float(h1));
    *(__nv_bfloat162*)(hi + o) = hv;
    *(__nv_bfloat162*)(lo + o) = lv;
}

// ---------------- generic split-bf16/fp16 HMMA GEMM ------------------------------
// AS: A single   BS: B single   HALF: fp16 MMA for Ah*Bh  (2-stage pipeline, R11 layout)
// Dual-A: if j0 >= aSwitch, use (Ah2, Al2) instead of (Ah, Al).
// EPI 0: fp32 store (+biasCol/+biasRow)
// EPI 2: exp -> bf16 quantize -> colsum atomics + staged bf16 store
// EPI 3: fp32 atomicAdd (split-K partials)
// EPI 4: fp32 store (+biasRow) + per-channel sum/sumsq atomics (fused BN stats)
#define TROW 80
#define TILE_BYTES (128*TROW)
#define OFF_AH 0
#define OFF_AL (TILE_BYTES)
#define OFF_BH (2*TILE_BYTES)
#define OFF_BL (3*TILE_BYTES)
#define BUF_BYTES (4*TILE_BYTES)
#define SMEM_TOT (2*BUF_BYTES)
#define EROW 136

template <int AS, int BS>
__device__ __forceinline__ void copy_chunk(uint32_t sb, int buf,
    const __nv_bfloat16* Ah, const __nv_bfloat16* Al, int i0,
    const __nv_bfloat16* Bh, const __nv_bfloat16* Bl, int j0, int Nn,
    int K, int k0, int tid)
{
    uint32_t base = sb + buf * BUF_BYTES;
#pragma unroll
    for (int i = 0; i < 2; i++) {
        int e = tid + i * 256;
        int r = e >> 2, seg = e & 3;
        uint32_t doff = r * TROW + seg * 16;
        size_t asrc = (size_t)(i0 + r) * K + k0 + seg * 8;
        cpa16(base + OFF_AH + doff, Ah + asrc, 16);
        if (!AS) cpa16(base + OFF_AL + doff, Al + asrc, 16);
        int brow = j0 + r;
        int sz = (brow < Nn) ? 16 : 0;
        int brc = (brow < Nn) ? brow : (Nn - 1);
        size_t bsrc = (size_t)brc * K + k0 + seg * 8;
        cpa16(base + OFF_BH + doff, Bh + bsrc, sz);
        if (!BS) cpa16(base + OFF_BL + doff, Bl + bsrc, sz);
    }
}

template <int EPI, int AS, int BS, int HALF>
__global__ void __launch_bounds__(256, 2)
mma_gemm(const __nv_bfloat16* __restrict__ Ah, const __nv_bfloat16* __restrict__ Al,
         const __nv_bfloat16* __restrict__ Ah2, const __nv_bfloat16* __restrict__ Al2,
         int aSwitch, size_t strA,
         const __nv_bfloat16* __restrict__ Bh, const __nv_bfloat16* __restrict__ Bl, size_t strB,
         int M, int Nn, int K, int ksplits,
         const float* __restrict__ biasCol, const float* __restrict__ biasRow,
         float* __restrict__ outF,
         __nv_bfloat16* __restrict__ outHi, __nv_bfloat16* __restrict__ outLo,
         size_t strO, int ldO,
         float* __restrict__ colsum,
         float* __restrict__ bnsum, float* __restrict__ bnsumsq)
{
    extern __shared__ __align__(128) char smem[];
    const uint32_t sb = smem_u32(smem);
    const int tid = threadIdx.x, lane = tid & 31, wid = tid >> 5;
    const int wm = wid >> 2, wn = wid & 3;
    const int z  = blockIdx.z;
    const int ksid = blockIdx.x % ksplits;
    const int i0 = blockIdx.y * 128, j0 = (blockIdx.x / ksplits) * 128;
    const int kLen = K / ksplits;      // must be a multiple of 32
    const int kOff = ksid * kLen;

    const __nv_bfloat16* Asel_h = (j0 >= aSwitch) ? Ah2 : Ah;
    const __nv_bfloat16* Asel_l = (j0 >= aSwitch) ? Al2 : Al;
    const __nv_bfloat16* Ahz = Asel_h + (size_t)z * strA;
    const __nv_bfloat16* Alz = Asel_l + (size_t)z * strA;
    const __nv_bfloat16* Bhz = Bh + (size_t)z * strB;
    const __nv_bfloat16* Blz = Bl + (size_t)z * strB;

    float acc[4][4][4];
#pragma unroll
    for (int a = 0; a < 4; a++)
#pragma unroll
        for (int b = 0; b < 4; b++)
#pragma unroll
            for (int c = 0; c < 4; c++) acc[a][b][c] = 0.f;

    const uint32_t aBase = sb + (uint32_t)((wm * 64 + (lane & 15)) * TROW + (lane >> 4) * 16);
    const uint32_t bBase = sb + (uint32_t)((wn * 32 + (lane & 7) + ((lane & 16) ? 8 : 0)) * TROW
                                           + ((lane & 8) ? 16 : 0));

    const int nch = kLen / 32;
    copy_chunk<AS, BS>(sb, 0, Ahz, Alz, i0, Bhz, Blz, j0, Nn, K, kOff, tid);
    cp_commit();
    for (int ch = 0; ch < nch; ch++) {
        cp_wait0();
        __syncthreads();
        if (ch + 1 < nch) {
            copy_chunk<AS, BS>(sb, (ch + 1) & 1, Ahz, Alz, i0, Bhz, Blz, j0, Nn, K,
                               kOff + (ch + 1) * 32, tid);
            cp_commit();
        }
        const uint32_t buf = (uint32_t)((ch & 1) * BUF_BYTES);
#pragma unroll
        for (int ks = 0; ks < 2; ks++) {
            uint32_t bh[8], bl[8];
#pragma unroll
            for (int grp = 0; grp < 2; grp++) {
                ldm4(&bh[grp * 4], bBase + buf + OFF_BH + grp * (16 * TROW) + ks * 32);
                if (!BS)
                    ldm4(&bl[grp * 4], bBase + buf + OFF_BL + grp * (16 * TROW) + ks * 32);
            }
#pragma unroll
            for (int am = 0; am < 4; am++) {
                uint32_t ah4[4], al4[4];
                ldm4(ah4, aBase + buf + OFF_AH + am * (16 * TROW) + ks * 32);
                if (!AS)
                    ldm4(al4, aBase + buf + OFF_AL + am * (16 * TROW) + ks * 32);
#pragma unroll
                for (int bn = 0; bn < 4; bn++) {
                    if (HALF) mma_fp16(acc[am][bn], ah4, bh[bn * 2], bh[bn * 2 + 1]);
                    else      mma_bf16(acc[am][bn], ah4, bh[bn * 2], bh[bn * 2 + 1]);
                }
                if (!BS) {
#pragma unroll
                    for (int bn = 0; bn < 4; bn++)
                        mma_bf16(acc[am][bn], ah4, bl[bn * 2], bl[bn * 2 + 1]);
                }
                if (!AS) {
#pragma unroll
                    for (int bn = 0; bn < 4; bn++)
                        mma_bf16(acc[am][bn], al4, bh[bn * 2], bh[bn * 2 + 1]);
                }
            }
        }
    }

    // ---- epilogue ----
    const int q    = lane >> 2;
    const int rloc = wm * 64 + q;
    const int cloc = wn * 32 + (lane & 3) * 2;

    if (EPI == 2) {
        __syncthreads();
        __nv_bfloat16* sh = (__nv_bfloat16*)smem;                       // [128][EROW]
        float cs[4][2];
#pragma unroll
        for (int bn = 0; bn < 4; bn++) { cs[bn][0] = 0.f; cs[bn][1] = 0.f; }
#pragma unroll
        for (int am = 0; am < 4; am++) {
            int rl = rloc + am * 16;
#pragma unroll
            for (int bn = 0; bn < 4; bn++) {
                int jl = cloc + bn * 8;
                __nv_bfloat16 h0 = __float2bfloat16(__expf(acc[am][bn][0]));
                __nv_bfloat16 h1 = __float2bfloat16(__expf(acc[am][bn][1]));
                __nv_bfloat16 h2 = __float2bfloat16(__expf(acc[am][bn][2]));
                __nv_bfloat16 h3 = __float2bfloat16(__expf(acc[am][bn][3]));
                cs[bn][0] += __bfloat162float(h0) + __bfloat162float(h2);
                cs[bn][1] += __bfloat162float(h1) + __bfloat162float(h3);
                __nv_bfloat162 hv01; hv01.x = h0; hv01.y = h1;
                __nv_bfloat162 hv23; hv23.x = h2; hv23.y = h3;
                *(__nv_bfloat162*)&sh[rl * EROW + jl]       = hv01;
                *(__nv_bfloat162*)&sh[(rl + 8) * EROW + jl] = hv23;
            }
        }
#pragma unroll
        for (int bn = 0; bn < 4; bn++)
#pragma unroll
            for (int jj = 0; jj < 2; jj++) {
                float v = cs[bn][jj];
                v += __shfl_xor_sync(0xffffffffu, v, 4);
                v += __shfl_xor_sync(0xffffffffu, v, 8);
                v += __shfl_xor_sync(0xffffffffu, v, 16);
                if (q == 0) {
                    int jg = j0 + cloc + bn * 8 + jj;
                    if (jg < Nn) atomicAdd(&colsum[z * Nn + jg], v);
                }
            }
        __syncthreads();
#pragma unroll
        for (int it = 0; it < 8; it++) {
            int e = it * 256 + tid;
            int r = e >> 4, s = e & 15;
            int jg = j0 + s * 8;
            if (jg < Nn) {
                size_t o = (size_t)z * strO + (size_t)(i0 + r) * ldO + jg;
                *(uint4*)(outHi + o) = *(const uint4*)&sh[r * EROW + s * 8];
            }
        }
    } else if (EPI == 3) {
#pragma unroll
        for (int am = 0; am < 4; am++) {
            int ig0 = i0 + rloc + am * 16;
#pragma unroll
            for (int bn = 0; bn < 4; bn++) {
                int jg = j0 + cloc + bn * 8;
                if (jg < Nn) {
                    size_t o0 = (size_t)z * strO + (size_t)ig0 * ldO + jg;
                    atomicAdd(outF + o0,     acc[am][bn][0]);
                    atomicAdd(outF + o0 + 1, acc[am][bn][1]);
                    atomicAdd(outF + o0 + (size_t)8 * ldO,     acc[am][bn][2]);
                    atomicAdd(outF + o0 + (size_t)8 * ldO + 1, acc[am][bn][3]);
                }
            }
        }
    } else {  // EPI 0 / 4
#pragma unroll
        for (int am = 0; am < 4; am++) {
            int ig0 = i0 + rloc + am * 16;
            float br0 = biasRow ? biasRow[ig0]     : 0.f;
            float br1 = biasRow ? biasRow[ig0 + 8] : 0.f;
            float sA = 0.f, sqA = 0.f, sB = 0.f, sqB = 0.f;
#pragma unroll
            for (int bn = 0; bn < 4; bn++) {
                int jg = j0 + cloc + bn * 8;
                if (jg < Nn) {
                    float bc0 = biasCol ? biasCol[jg]     : 0.f;
                    float bc1 = biasCol ? biasCol[jg + 1] : 0.f;
                    float v0 = acc[am][bn][0] + bc0 + br0;
                    float v1 = acc[am][bn][1] + bc1 + br0;
                    float v2 = acc[am][bn][2] + bc0 + br1;
                    float v3 = acc[am][bn][3] + bc1 + br1;
                    size_t o0 = (size_t)z * strO + (size_t)ig0 * ldO + jg;
                    *(float2*)(outF + o0) = make_float2(v0, v1);
                    *(float2*)(outF + o0 + (size_t)8 * ldO) = make_float2(v2, v3);
                    if (EPI == 4) {
                        sA += v0 + v1;  sqA += v0 * v0 + v1 * v1;
                        sB += v2 + v3;  sqB += v2 * v2 + v3 * v3;
                    }
                }
            }
            if (EPI == 4) {
                sA  += __shfl_xor_sync(0xffffffffu, sA, 1);
                sA  += __shfl_xor_sync(0xffffffffu, sA, 2);
                sqA += __shfl_xor_sync(0xffffffffu, sqA, 1);
                sqA += __shfl_xor_sync(0xffffffffu, sqA, 2);
                sB  += __shfl_xor_sync(0xffffffffu, sB, 1);
                sB  += __shfl_xor_sync(0xffffffffu, sB, 2);
                sqB += __shfl_xor_sync(0xffffffffu, sqB, 1);
                sqB += __shfl_xor_sync(0xffffffffu, sqB, 2);
                if ((lane & 3) == 0) {
                    atomicAdd(&bnsum[ig0],       sA);
                    atomicAdd(&bnsumsq[ig0],     sqA);
                    atomicAdd(&bnsum[ig0 + 8],   sB);
                    atomicAdd(&bnsumsq[ig0 + 8], sqB);
                }
            }
        }
    }
}

// ---------------- prep / pool / BN kernels --------------------------------------
// which: 0 -> phi_w rows 0-127; 1 -> g_w rows 128-255; 2 -> theta_w rows 256-383; 3 -> W_w
__global__ void split_weights(const float* __restrict__ p_w, const float* __restrict__ g_w,
                              const float* __restrict__ t_w, const float* __restrict__ W_w)
{
    int i = blockIdx.x * 256 + threadIdx.x;
    int which = blockIdx.y;
    const float* in = (which == 0) ? p_w : (which == 1) ? g_w : (which == 2) ? t_w : W_w;
    __nv_bfloat16* ho = (which == 3) ? d_Ww_h : (d_cw_h + which * CI_ * C_);
    __nv_bfloat16* lo = (which == 3) ? d_Ww_l : (d_cw_l + which * CI_ * C_);
    float v = in[i];
    __nv_bfloat16 h = __float2bfloat16(v);
    ho[i] = h;
    lo[i] = __float2bfloat16(v - __bfloat162float(h));
}

__global__ void stack_bias(const float* __restrict__ phi_b, const float* __restrict__ g_b,
                           const float* __restrict__ theta_b)
{
    int i = threadIdx.x;            // 384 threads
    d_c_bias[i] = (i < CI_) ? phi_b[i] : (i < 2 * CI_) ? g_b[i - CI_] : theta_b[i - 2 * CI_];
}

__global__ void transpose_split(const float* __restrict__ in,
                                __nv_bfloat16* __restrict__ hi, __nv_bfloat16* __restrict__ lo)
{
    __shared__ float t[32][33];
    int z  = blockIdx.z;
    int n0 = blockIdx.x * 32, c0 = blockIdx.y * 32;
    int tx = threadIdx.x, ty = threadIdx.y;
    const float* ip = in + (size_t)z * C_ * N_;
#pragma unroll
    for (int i = 0; i < 4; i++)
        t[ty + 8 * i][tx] = ip[(size_t)(c0 + ty + 8 * i) * N_ + n0 + tx];
    __syncthreads();
#pragma unroll
    for (int i = 0; i < 4; i++) {
        float v = t[tx][ty + 8 * i];
        __nv_bfloat16 h = __float2bfloat16(v);
        size_t o = ((size_t)z * N_ + n0 + ty + 8 * i) * C_ + c0 + tx;
        hi[o] = h;
        lo[o] = __float2bfloat16(v - __bfloat162float(h));
    }
}

// theta slice of convN (cols 256-383) -> fp16 (z, N, CI)
__global__ void theta_cvt()
{
    int idx = blockIdx.x * 256 + threadIdx.x;     // B_*N_*CI_/2 pairs
    if (idx >= B_ * N_ * CI_ / 2) return;
    int ci2 = idx % (CI_ / 2);
    int n   = idx / (CI_ / 2);
    const float2 v = *(const float2*)&d_convN[(size_t)n * CW_ + 2 * CI_ + ci2 * 2];
    __half2 h; h.x = __float2half(v.x); h.y = __float2half(v.y);
    *(__half2*)&d_thT[(size_t)n * CI_ + ci2 * 2] = h;
}

// phi: pooled from convN cols 0-127 -> single fp16 (z, NS, CI)
__global__ void pool_phi_k()
{
    int m = blockIdx.x, z = blockIdx.y, ci = threadIdx.x;
    int t  = m / (HS_ * WS_);
    int r  = m % (HS_ * WS_);
    int h2 = r / WS_, w2 = r % WS_;
    int n00 = t * (H_ * W_) + 2 * h2 * W_ + 2 * w2;
    const float* p = d_convN + (size_t)z * N_ * CW_ + ci;
    const int ld = CW_;
    float v = fmaxf(fmaxf(p[(size_t)n00 * ld],        p[(size_t)(n00 + 1) * ld]),
                    fmaxf(p[(size_t)(n00 + W_) * ld], p[(size_t)(n00 + W_ + 1) * ld]));
    d_phiP[((size_t)z * NS_ + m) * CI_ + ci] = __float2half(v);
}

// g: pooled from convN cols 128-255 -> fp32 (z, NS, CI)
__global__ void pool_g_k()
{
    int m = blockIdx.x, z = blockIdx.y, ci = threadIdx.x;
    int t  = m / (HS_ * WS_);
    int r  = m % (HS_ * WS_);
    int h2 = r / WS_, w2 = r % WS_;
    int n00 = t * (H_ * W_) + 2 * h2 * W_ + 2 * w2;
    const float* p = d_convN + (size_t)z * N_ * CW_ + CI_ + ci;
    const int ld = CW_;
    float v = fmaxf(fmaxf(p[(size_t)n00 * ld],        p[(size_t)(n00 + 1) * ld]),
                    fmaxf(p[(size_t)(n00 + W_) * ld], p[(size_t)(n00 + W_ + 1) * ld]));
    d_gpool[((size_t)z * NS_ + m) * CI_ + ci] = v;
}

// gpool (z, NS, CI) fp32 / colsum -> gs (z, CI, NS) bf16 hi/lo
__global__ void scale_tr_split_g()
{
    __shared__ float t[32][33];
    int z  = blockIdx.z;
    int m0 = blockIdx.x * 32, c0 = blockIdx.y * 32;
    int tx = threadIdx.x, ty = threadIdx.y;
#pragma unroll
    for (int i = 0; i < 4; i++)
        t[ty + 8 * i][tx] = d_gpool[((size_t)z * NS_ + m0 + ty + 8 * i) * CI_ + c0 + tx];
    __syncthreads();
    float inv = 1.0f / d_colsum[z * NS_ + m0 + tx];
#pragma unroll
    for (int i = 0; i < 4; i++) {
        float v = t[tx][ty + 8 * i] * inv;
        __nv_bfloat16 h = __float2bfloat16(v);
        size_t o = ((size_t)z * CI_ + c0 + ty + 8 * i) * NS_ + m0 + tx;
        d_gs_h[o] = h;
        d_gs_l[o] = __float2bfloat16(v - __bfloat162float(h));
    }
}

// y fp32 -> split bf16
__global__ void y_convert()
{
    int i2 = blockIdx.x * 256 + threadIdx.x;
    if (i2 >= B_ * N_ * CI_ / 2) return;
    float2 v = *(const float2*)&d_yF[i2 * 2];
    store_split2(d_y_h, d_y_l, (size_t)i2 * 2, v.x, v.y);
}

__global__ void bn_finalize(const float* __restrict__ gamma, const float* __restrict__ beta)
{
    int c = threadIdx.x;
    float cnt  = (float)(B_ * N_);
    float mean = d_bnsum[c] / cnt;
    float var  = d_bnsumsq[c] / cnt - mean * mean;
    float inv  = rsqrtf(var + 1e-5f);
    float g    = gamma[c] * inv;
    d_bnscale[c] = g;
    d_bnbias[c]  = beta[c] - mean * g;
}

__global__ void final_kernel(const float* __restrict__ x, float* __restrict__ out)
{
    int idx4 = blockIdx.x * blockDim.x + threadIdx.x;
    if (idx4 >= (B_ * C_ * N_) / 4) return;
    int idx = idx4 * 4;
    int c = (idx / N_) % C_;
    float sc = d_bnscale[c], bi = d_bnbias[c];
    float4 w  = *(const float4*)&d_wy[idx];
    float4 xv = *(const float4*)&x[idx];
    float4 o;
    o.x = fmaf(w.x, sc, bi) + xv.x;
    o.y = fmaf(w.y, sc, bi) + xv.y;
    o.z = fmaf(w.z, sc, bi) + xv.z;
    o.w = fmaf(w.w, sc, bi) + xv.w;
    *(float4*)&out[idx] = o;
}

// ---------------- launch ---------------------------------------------------------
extern "C" void kernel_launch(void* const* d_in, const int* in_sizes, int n_in,
                              void* d_out, int out_size)
{
    const float* x       = (const float*)d_in[0];
    const float* mp      = (const float*)d_in[1];
    const float* g_w     = (const float*)d_in[2];
    const float* g_b     = (const float*)d_in[3];
    const float* theta_w = (const float*)d_in[4];
    const float* theta_b = (const float*)d_in[5];
    const float* phi_w   = (const float*)d_in[6];
    const float* phi_b   = (const float*)d_in[7];
    const float* W_w     = (const float*)d_in[8];
    const float* W_b     = (const float*)d_in[9];
    const float* gamma   = (const float*)d_in[10];
    const float* beta    = (const float*)d_in[11];
    float* out = (float*)d_out;

    __nv_bfloat16 *xT_h, *xT_l, *mT_h, *mT_l, *cw_h, *cw_l;
    __nv_bfloat16 *Ww_h, *Ww_l, *gs_h, *gs_l, *ef_h, *y_h, *y_l;
    __half *thT, *phiP;
    float *convN, *wy, *colsum, *c_bias, *yF, *bnsum, *bnsumsq;
    cudaGetSymbolAddress((void**)&xT_h, d_xT_h);   cudaGetSymbolAddress((void**)&xT_l, d_xT_l);
    cudaGetSymbolAddress((void**)&mT_h, d_mT_h);   cudaGetSymbolAddress((void**)&mT_l, d_mT_l);
    cudaGetSymbolAddress((void**)&cw_h, d_cw_h);   cudaGetSymbolAddress((void**)&cw_l, d_cw_l);
    cudaGetSymbolAddress((void**)&Ww_h, d_Ww_h);   cudaGetSymbolAddress((void**)&Ww_l, d_Ww_l);
    cudaGetSymbolAddress((void**)&thT, d_thT);     cudaGetSymbolAddress((void**)&phiP, d_phiP);
    cudaGetSymbolAddress((void**)&gs_h, d_gs_h);   cudaGetSymbolAddress((void**)&gs_l, d_gs_l);
    cudaGetSymbolAddress((void**)&ef_h, d_ef_h);
    cudaGetSymbolAddress((void**)&y_h, d_y_h);     cudaGetSymbolAddress((void**)&y_l, d_y_l);
    cudaGetSymbolAddress((void**)&convN, d_convN); cudaGetSymbolAddress((void**)&wy, d_wy);
    cudaGetSymbolAddress((void**)&colsum, d_colsum);
    cudaGetSymbolAddress((void**)&c_bias, d_c_bias);
    cudaGetSymbolAddress((void**)&yF, d_yF);
    cudaGetSymbolAddress((void**)&bnsum, d_bnsum);
    cudaGetSymbolAddress((void**)&bnsumsq, d_bnsumsq);

    cudaFuncSetAttribute((const void*)mma_gemm<0,0,0,0>, cudaFuncAttributeMaxDynamicSharedMemorySize, SMEM_TOT);
    cudaFuncSetAttribute((const void*)mma_gemm<2,1,1,1>, cudaFuncAttributeMaxDynamicSharedMemorySize, SMEM_TOT);
    cudaFuncSetAttribute((const void*)mma_gemm<3,1,0,0>, cudaFuncAttributeMaxDynamicSharedMemorySize, SMEM_TOT);
    cudaFuncSetAttribute((const void*)mma_gemm<4,0,0,0>, cudaFuncAttributeMaxDynamicSharedMemorySize, SMEM_TOT);

    // prep
    split_weights<<<dim3(128, 4), 256>>>(phi_w, g_w, theta_w, W_w);
    stack_bias<<<1, CW_>>>(phi_b, g_b, theta_b);
    transpose_split<<<dim3(N_ / 32, C_ / 32, B_), dim3(32, 8)>>>(x,  xT_h, xT_l);
    transpose_split<<<dim3(N_ / 32, C_ / 32, B_), dim3(32, 8)>>>(mp, mT_h, mT_l);
    // merged phi+g+theta conv -> fp32 (z, N, 384); A = xT for j<256, mT for j>=256
    mma_gemm<0,0,0,0><<<dim3(3, N_ / 128, B_), 256, SMEM_TOT>>>(
        xT_h, xT_l, mT_h, mT_l, 2 * CI_, (size_t)N_ * C_,
        cw_h, cw_l, 0,
        N_, CW_, C_, 1, c_bias, nullptr,
        convN, nullptr, nullptr, (size_t)N_ * CW_, CW_, nullptr, nullptr, nullptr);
    cudaMemsetAsync(colsum, 0, B_ * NS_ * sizeof(float));
    cudaMemsetAsync(yF, 0, B_ * N_ * CI_ * sizeof(float));
    cudaMemsetAsync(bnsum, 0, C_ * sizeof(float));
    cudaMemsetAsync(bnsumsq, 0, C_ * sizeof(float));
    // theta -> fp16; pools
    theta_cvt<<<(B_ * N_ * CI_ / 2 + 255) / 256, 256>>>();
    pool_phi_k<<<dim3(NS_, B_), CI_>>>();
    pool_g_k<<<dim3(NS_, B_), CI_>>>();
    // f = exp(theta @ phi^T): fp16 single x single (1 product), colsum from quantized ef
    mma_gemm<2,1,1,1><<<dim3((NS_ + 127) / 128, N_ / 128, B_), 256, SMEM_TOT>>>(
        (const __nv_bfloat16*)thT, (const __nv_bfloat16*)thT,
        (const __nv_bfloat16*)thT, (const __nv_bfloat16*)thT, 1 << 30, (size_t)N_ * CI_,
        (const __nv_bfloat16*)phiP, (const __nv_bfloat16*)phiP, (size_t)NS_ * CI_,
        N_, NS_, CI_, 1, nullptr, nullptr,
        nullptr, ef_h, nullptr, (size_t)N_ * NS_, NS_, colsum, nullptr, nullptr);
    // g scaled by 1/Z, transposed, split bf16
    scale_tr_split_g<<<dim3(NS_ / 32, CI_ / 32, B_), dim3(32, 8)>>>();
    // y = ef @ gs^T: A single bf16 (2 products), split-K=7, fp32 atomic accumulation
    mma_gemm<3,1,0,0><<<dim3(7, N_ / 128, B_), 256, SMEM_TOT>>>(
        ef_h, ef_h, ef_h, ef_h, 1 << 30, (size_t)N_ * NS_,
        gs_h, gs_l, (size_t)CI_ * NS_,
        N_, CI_, NS_, 7, nullptr, nullptr,
        yF, nullptr, nullptr, (size_t)N_ * CI_, CI_, nullptr, nullptr, nullptr);
    // y -> split bf16
    y_convert<<<(B_ * N_ * CI_ / 2 + 255) / 256, 256>>>();
    // W_y = W_w @ y^T + W_b, fused BN stats
    mma_gemm<4,0,0,0><<<dim3(N_ / 128, C_ / 128, B_), 256, SMEM_TOT>>>(
        Ww_h, Ww_l, Ww_h, Ww_l, 1 << 30, (size_t)0,
        y_h, y_l, (size_t)N_ * CI_,
        C_, N_, CI_, 1, nullptr, W_b,
        wy, nullptr, nullptr, (size_t)C_ * N_, N_, nullptr, bnsum, bnsumsq);
    // BN finalize + residual
    bn_finalize<<<1, C_>>>(gamma, beta);
    final_kernel<<<(B_ * C_ * N_ / 4 + 255) / 256, 256>>>(x, out);
}

// round 16
// speedup vs baseline: 1.2268x; 1.0217x over previous
#include <cuda_runtime.h>
#include <cuda_bf16.h>
#include <cuda_fp16.h>
#include <cstdint>

#define B_   2
#define C_   256
#define CI_  128
#define T_   16
#define H_   28
#define W_   28
#define N_   12544
#define HS_  14
#define WS_  14
#define NS_  3136
#define CW_  (3*CI_)     // stacked conv output channels: [phi | g | theta]

typedef unsigned long long u64;

// ---------------- scratch (device globals) -------------------------------------
__device__ __align__(16) __nv_bfloat16 d_xT_h[B_*N_*C_],  d_xT_l[B_*N_*C_];
__device__ __align__(16) __nv_bfloat16 d_mT_h[B_*N_*C_],  d_mT_l[B_*N_*C_];
__device__ __align__(16) __nv_bfloat16 d_cw_h[CW_*C_],    d_cw_l[CW_*C_];
__device__ __align__(16) __nv_bfloat16 d_Ww_h[C_*CI_],    d_Ww_l[C_*CI_];
__device__ float d_c_bias[CW_];
__device__ __align__(16) float d_convN[B_*N_*2*CI_];      // (z, N, 256) fp32: phi|g
__device__ __align__(16) __half d_thT[B_*N_*CI_];         // theta fp16 (written by conv EPI 6)
__device__ __align__(16) __half d_phiP[B_*NS_*CI_];       // phi pooled fp16
__device__ __align__(16) float d_gpool[B_*NS_*CI_];
__device__ __align__(16) __nv_bfloat16 d_gs_h[B_*CI_*NS_], d_gs_l[B_*CI_*NS_];
__device__ __align__(16) __nv_bfloat16 d_ef_h[(size_t)B_*N_*NS_];   // exp(f) bf16 (157 MB)
__device__ float d_colsum[B_*NS_];
__device__ __align__(16) float d_yF[B_*N_*CI_];
__device__ __align__(16) __nv_bfloat16 d_y_h[B_*N_*CI_], d_y_l[B_*N_*CI_];
__device__ __align__(16) float d_wy[B_*C_*N_];
__device__ float d_bnsum[C_], d_bnsumsq[C_];
__device__ float d_bnscale[C_], d_bnbias[C_];

// ---------------- PTX helpers ---------------------------------------------------
__device__ __forceinline__ uint32_t smem_u32(const void* p) {
    uint32_t a;
    asm("{ .reg .u64 t; cvta.to.shared.u64 t, %1; cvt.u32.u64 %0, t; }" : "=r"(a) : "l"(p));
    return a;
}
__device__ __forceinline__ void cpa16(uint32_t d, const void* s, int sz) {
    asm volatile("cp.async.ca.shared.global [%0], [%1], 16, %2;" :: "r"(d), "l"(s), "r"(sz));
}
__device__ __forceinline__ void cp_commit() { asm volatile("cp.async.commit_group;" ::: "memory"); }
__device__ __forceinline__ void cp_wait0()  { asm volatile("cp.async.wait_group 0;"  ::: "memory"); }

__device__ __forceinline__ void ldm4(uint32_t* r, uint32_t a) {
    asm volatile("ldmatrix.sync.aligned.m8n8.x4.shared.b16 {%0,%1,%2,%3}, [%4];"
                 : "=r"(r[0]), "=r"(r[1]), "=r"(r[2]), "=r"(r[3]) : "r"(a));
}
__device__ __forceinline__ void mma_bf16(float* c, const uint32_t* a, uint32_t b0, uint32_t b1) {
    asm volatile("mma.sync.aligned.m16n8k16.row.col.f32.bf16.bf16.f32 "
                 "{%0,%1,%2,%3}, {%4,%5,%6,%7}, {%8,%9}, {%0,%1,%2,%3};"
                 : "+f"(c[0]), "+f"(c[1]), "+f"(c[2]), "+f"(c[3])
                 : "r"(a[0]), "r"(a[1]), "r"(a[2]), "r"(a[3]), "r"(b0), "r"(b1));
}
__device__ __forceinline__ void mma_fp16(float* c, const uint32_t* a, uint32_t b0, uint32_t b1) {
    asm volatile("mma.sync.aligned.m16n8k16.row.col.f32.f16.f16.f32 "
                 "{%0,%1,%2,%3}, {%4,%5,%6,%7}, {%8,%9}, {%0,%1,%2,%3};"
                 : "+f"(c[0]), "+f"(c[1]), "+f"(c[2]), "+f"(c[3])
                 : "r"(a[0]), "r"(a[1]), "r"(a[2]), "r"(a[3]), "r"(b0), "r"(b1));
}
__device__ __forceinline__ void store_split2(__nv_bfloat16* hi, __nv_bfloat16* lo,
                                             size_t o, float v0, float v1) {
    __nv_bfloat16 h0 = __float2bfloat16(v0), h1 = __float2bfloat16(v1);
    __nv_bfloat162 hv; hv.x = h0; hv.y = h1;
    __nv_bfloat162 lv;
    lv.x = __float2bfloat16(v0 - __bfloat162float(h0));
    lv.y = __float2bfloat16(v1 - __bfloat162float(h1));
    *(__nv_bfloat162*)(hi + o) = hv;
    *(__nv_bfloat162*)(lo + o) = lv;
}

// ---------------- generic split-bf16/fp16 HMMA GEMM ------------------------------
// AS: A single   BS: B single   HALF: fp16 MMA for Ah*Bh  (2-stage pipeline)
// Dual-A: if j0 >= aSwitch, use (Ah2, Al2).
// EPI 0: fp32 store (+biasCol/+biasRow)
// EPI 2: exp -> bf16 quantize -> colsum atomics + staged bf16 store
// EPI 3: fp32 atomicAdd (split-K partials)
// EPI 4: fp32 store (+biasRow) + per-channel sum/sumsq atomics (fused BN stats)
// EPI 6: fp32 store for jg < 2*CI (ldO), fp16 store to outHi(__half, ld CI_) for jg >= 2*CI
#define TROW 80
#define TILE_BYTES (128*TROW)
#define OFF_AH 0
#define OFF_AL (TILE_BYTES)
#define OFF_BH (2*TILE_BYTES)
#define OFF_BL (3*TILE_BYTES)
#define BUF_BYTES (4*TILE_BYTES)
#define SMEM_TOT (2*BUF_BYTES)
#define EROW 136

template <int AS, int BS>
__device__ __forceinline__ void copy_chunk(uint32_t sb, int buf,
    const __nv_bfloat16* Ah, const __nv_bfloat16* Al, int i0,
    const __nv_bfloat16* Bh, const __nv_bfloat16* Bl, int j0, int Nn,
    int K, int k0, int tid)
{
    uint32_t base = sb + buf * BUF_BYTES;
#pragma unroll
    for (int i = 0; i < 2; i++) {
        int e = tid + i * 256;
        int r = e >> 2, seg = e & 3;
        uint32_t doff = r * TROW + seg * 16;
        size_t asrc = (size_t)(i0 + r) * K + k0 + seg * 8;
        cpa16(base + OFF_AH + doff, Ah + asrc, 16);
        if (!AS) cpa16(base + OFF_AL + doff, Al + asrc, 16);
        int brow = j0 + r;
        int sz = (brow < Nn) ? 16 : 0;
        int brc = (brow < Nn) ? brow : (Nn - 1);
        size_t bsrc = (size_t)brc * K + k0 + seg * 8;
        cpa16(base + OFF_BH + doff, Bh + bsrc, sz);
        if (!BS) cpa16(base + OFF_BL + doff, Bl + bsrc, sz);
    }
}

template <int EPI, int AS, int BS, int HALF>
__global__ void __launch_bounds__(256, 2)
mma_gemm(const __nv_bfloat16* __restrict__ Ah, const __nv_bfloat16* __restrict__ Al,
         const __nv_bfloat16* __restrict__ Ah2, const __nv_bfloat16* __restrict__ Al2,
         int aSwitch, size_t strA,
         const __nv_bfloat16* __restrict__ Bh, const __nv_bfloat16* __restrict__ Bl, size_t strB,
         int M, int Nn, int K, int ksplits,
         const float* __restrict__ biasCol, const float* __restrict__ biasRow,
         float* __restrict__ outF,
         __nv_bfloat16* __restrict__ outHi, __nv_bfloat16* __restrict__ outLo,
         size_t strO, int ldO,
         float* __restrict__ colsum,
         float* __restrict__ bnsum, float* __restrict__ bnsumsq)
{
    extern __shared__ __align__(128) char smem[];
    const uint32_t sb = smem_u32(smem);
    const int tid = threadIdx.x, lane = tid & 31, wid = tid >> 5;
    const int wm = wid >> 2, wn = wid & 3;
    const int z  = blockIdx.z;
    const int ksid = blockIdx.x % ksplits;
    const int i0 = blockIdx.y * 128, j0 = (blockIdx.x / ksplits) * 128;
    const int kLen = K / ksplits;
    const int kOff = ksid * kLen;

    const __nv_bfloat16* Asel_h = (j0 >= aSwitch) ? Ah2 : Ah;
    const __nv_bfloat16* Asel_l = (j0 >= aSwitch) ? Al2 : Al;
    const __nv_bfloat16* Ahz = Asel_h + (size_t)z * strA;
    const __nv_bfloat16* Alz = Asel_l + (size_t)z * strA;
    const __nv_bfloat16* Bhz = Bh + (size_t)z * strB;
    const __nv_bfloat16* Blz = Bl + (size_t)z * strB;

    float acc[4][4][4];
#pragma unroll
    for (int a = 0; a < 4; a++)
#pragma unroll
        for (int b = 0; b < 4; b++)
#pragma unroll
            for (int c = 0; c < 4; c++) acc[a][b][c] = 0.f;

    const uint32_t aBase = sb + (uint32_t)((wm * 64 + (lane & 15)) * TROW + (lane >> 4) * 16);
    const uint32_t bBase = sb + (uint32_t)((wn * 32 + (lane & 7) + ((lane & 16) ? 8 : 0)) * TROW
                                           + ((lane & 8) ? 16 : 0));

    const int nch = kLen / 32;
    copy_chunk<AS, BS>(sb, 0, Ahz, Alz, i0, Bhz, Blz, j0, Nn, K, kOff, tid);
    cp_commit();
    for (int ch = 0; ch < nch; ch++) {
        cp_wait0();
        __syncthreads();
        if (ch + 1 < nch) {
            copy_chunk<AS, BS>(sb, (ch + 1) & 1, Ahz, Alz, i0, Bhz, Blz, j0, Nn, K,
                               kOff + (ch + 1) * 32, tid);
            cp_commit();
        }
        const uint32_t buf = (uint32_t)((ch & 1) * BUF_BYTES);
#pragma unroll
        for (int ks = 0; ks < 2; ks++) {
            uint32_t bh[8], bl[8];
#pragma unroll
            for (int grp = 0; grp < 2; grp++) {
                ldm4(&bh[grp * 4], bBase + buf + OFF_BH + grp * (16 * TROW) + ks * 32);
                if (!BS)
                    ldm4(&bl[grp * 4], bBase + buf + OFF_BL + grp * (16 * TROW) + ks * 32);
            }
#pragma unroll
            for (int am = 0; am < 4; am++) {
                uint32_t ah4[4], al4[4];
                ldm4(ah4, aBase + buf + OFF_AH + am * (16 * TROW) + ks * 32);
                if (!AS)
                    ldm4(al4, aBase + buf + OFF_AL + am * (16 * TROW) + ks * 32);
#pragma unroll
                for (int bn = 0; bn < 4; bn++) {
                    if (HALF) mma_fp16(acc[am][bn], ah4, bh[bn * 2], bh[bn * 2 + 1]);
                    else      mma_bf16(acc[am][bn], ah4, bh[bn * 2], bh[bn * 2 + 1]);
                }
                if (!BS) {
#pragma unroll
                    for (int bn = 0; bn < 4; bn++)
                        mma_bf16(acc[am][bn], ah4, bl[bn * 2], bl[bn * 2 + 1]);
                }
                if (!AS) {
#pragma unroll
                    for (int bn = 0; bn < 4; bn++)
                        mma_bf16(acc[am][bn], al4, bh[bn * 2], bh[bn * 2 + 1]);
                }
            }
        }
    }

    // ---- epilogue ----
    const int q    = lane >> 2;
    const int rloc = wm * 64 + q;
    const int cloc = wn * 32 + (lane & 3) * 2;

    if (EPI == 2) {
        __syncthreads();
        __nv_bfloat16* sh = (__nv_bfloat16*)smem;
        float cs[4][2];
#pragma unroll
        for (int bn = 0; bn < 4; bn++) { cs[bn][0] = 0.f; cs[bn][1] = 0.f; }
#pragma unroll
        for (int am = 0; am < 4; am++) {
            int rl = rloc + am * 16;
#pragma unroll
            for (int bn = 0; bn < 4; bn++) {
                int jl = cloc + bn * 8;
                __nv_bfloat16 h0 = __float2bfloat16(__expf(acc[am][bn][0]));
                __nv_bfloat16 h1 = __float2bfloat16(__expf(acc[am][bn][1]));
                __nv_bfloat16 h2 = __float2bfloat16(__expf(acc[am][bn][2]));
                __nv_bfloat16 h3 = __float2bfloat16(__expf(acc[am][bn][3]));
                cs[bn][0] += __bfloat162float(h0) + __bfloat162float(h2);
                cs[bn][1] += __bfloat162float(h1) + __bfloat162float(h3);
                __nv_bfloat162 hv01; hv01.x = h0; hv01.y = h1;
                __nv_bfloat162 hv23; hv23.x = h2; hv23.y = h3;
                *(__nv_bfloat162*)&sh[rl * EROW + jl]       = hv01;
                *(__nv_bfloat162*)&sh[(rl + 8) * EROW + jl] = hv23;
            }
        }
#pragma unroll
        for (int bn = 0; bn < 4; bn++)
#pragma unroll
            for (int jj = 0; jj < 2; jj++) {
                float v = cs[bn][jj];
                v += __shfl_xor_sync(0xffffffffu, v, 4);
                v += __shfl_xor_sync(0xffffffffu, v, 8);
                v += __shfl_xor_sync(0xffffffffu, v, 16);
                if (q == 0) {
                    int jg = j0 + cloc + bn * 8 + jj;
                    if (jg < Nn) atomicAdd(&colsum[z * Nn + jg], v);
                }
            }
        __syncthreads();
#pragma unroll
        for (int it = 0; it < 8; it++) {
            int e = it * 256 + tid;
            int r = e >> 4, s = e & 15;
            int jg = j0 + s * 8;
            if (jg < Nn) {
                size_t o = (size_t)z * strO + (size_t)(i0 + r) * ldO + jg;
                *(uint4*)(outHi + o) = *(const uint4*)&sh[r * EROW + s * 8];
            }
        }
    } else if (EPI == 3) {
#pragma unroll
        for (int am = 0; am < 4; am++) {
            int ig0 = i0 + rloc + am * 16;
#pragma unroll
            for (int bn = 0; bn < 4; bn++) {
                int jg = j0 + cloc + bn * 8;
                if (jg < Nn) {
                    size_t o0 = (size_t)z * strO + (size_t)ig0 * ldO + jg;
                    atomicAdd(outF + o0,     acc[am][bn][0]);
                    atomicAdd(outF + o0 + 1, acc[am][bn][1]);
                    atomicAdd(outF + o0 + (size_t)8 * ldO,     acc[am][bn][2]);
                    atomicAdd(outF + o0 + (size_t)8 * ldO + 1, acc[am][bn][3]);
                }
            }
        }
    } else if (EPI == 6) {
        // conv: fp32 (phi|g) for jg < 2*CI_, fp16 theta for jg >= 2*CI_
        __half* outH = (__half*)outHi;
#pragma unroll
        for (int am = 0; am < 4; am++) {
            int ig0 = i0 + rloc + am * 16;
#pragma unroll
            for (int bn = 0; bn < 4; bn++) {
                int jg = j0 + cloc + bn * 8;
                float bc0 = biasCol[jg];
                float bc1 = biasCol[jg + 1];
                float v0 = acc[am][bn][0] + bc0;
                float v1 = acc[am][bn][1] + bc1;
                float v2 = acc[am][bn][2] + bc0;
                float v3 = acc[am][bn][3] + bc1;
                if (jg < 2 * CI_) {
                    size_t o0 = (size_t)z * strO + (size_t)ig0 * ldO + jg;
                    *(float2*)(outF + o0) = make_float2(v0, v1);
                    *(float2*)(outF + o0 + (size_t)8 * ldO) = make_float2(v2, v3);
                } else {
                    int jc = jg - 2 * CI_;
                    size_t o0 = ((size_t)z * M + ig0) * CI_ + jc;
                    __half2 h01; h01.x = __float2half(v0); h01.y = __float2half(v1);
                    __half2 h23; h23.x = __float2half(v2); h23.y = __float2half(v3);
                    *(__half2*)(outH + o0) = h01;
                    *(__half2*)(outH + o0 + (size_t)8 * CI_) = h23;
                }
            }
        }
    } else {  // EPI 0 / 4
#pragma unroll
        for (int am = 0; am < 4; am++) {
            int ig0 = i0 + rloc + am * 16;
            float br0 = biasRow ? biasRow[ig0]     : 0.f;
            float br1 = biasRow ? biasRow[ig0 + 8] : 0.f;
            float sA = 0.f, sqA = 0.f, sB = 0.f, sqB = 0.f;
#pragma unroll
            for (int bn = 0; bn < 4; bn++) {
                int jg = j0 + cloc + bn * 8;
                if (jg < Nn) {
                    float bc0 = biasCol ? biasCol[jg]     : 0.f;
                    float bc1 = biasCol ? biasCol[jg + 1] : 0.f;
                    float v0 = acc[am][bn][0] + bc0 + br0;
                    float v1 = acc[am][bn][1] + bc1 + br0;
                    float v2 = acc[am][bn][2] + bc0 + br1;
                    float v3 = acc[am][bn][3] + bc1 + br1;
                    size_t o0 = (size_t)z * strO + (size_t)ig0 * ldO + jg;
                    *(float2*)(outF + o0) = make_float2(v0, v1);
                    *(float2*)(outF + o0 + (size_t)8 * ldO) = make_float2(v2, v3);
                    if (EPI == 4) {
                        sA += v0 + v1;  sqA += v0 * v0 + v1 * v1;
                        sB += v2 + v3;  sqB += v2 * v2 + v3 * v3;
                    }
                }
            }
            if (EPI == 4) {
                sA  += __shfl_xor_sync(0xffffffffu, sA, 1);
                sA  += __shfl_xor_sync(0xffffffffu, sA, 2);
                sqA += __shfl_xor_sync(0xffffffffu, sqA, 1);
                sqA += __shfl_xor_sync(0xffffffffu, sqA, 2);
                sB  += __shfl_xor_sync(0xffffffffu, sB, 1);
                sB  += __shfl_xor_sync(0xffffffffu, sB, 2);
                sqB += __shfl_xor_sync(0xffffffffu, sqB, 1);
                sqB += __shfl_xor_sync(0xffffffffu, sqB, 2);
                if ((lane & 3) == 0) {
                    atomicAdd(&bnsum[ig0],       sA);
                    atomicAdd(&bnsumsq[ig0],     sqA);
                    atomicAdd(&bnsum[ig0 + 8],   sB);
                    atomicAdd(&bnsumsq[ig0 + 8], sqB);
                }
            }
        }
    }
}

// ---------------- prep / pool / BN kernels --------------------------------------
__global__ void split_weights(const float* __restrict__ p_w, const float* __restrict__ g_w,
                              const float* __restrict__ t_w, const float* __restrict__ W_w)
{
    int i = blockIdx.x * 256 + threadIdx.x;
    int which = blockIdx.y;
    const float* in = (which == 0) ? p_w : (which == 1) ? g_w : (which == 2) ? t_w : W_w;
    __nv_bfloat16* ho = (which == 3) ? d_Ww_h : (d_cw_h + which * CI_ * C_);
    __nv_bfloat16* lo = (which == 3) ? d_Ww_l : (d_cw_l + which * CI_ * C_);
    float v = in[i];
    __nv_bfloat16 h = __float2bfloat16(v);
    ho[i] = h;
    lo[i] = __float2bfloat16(v - __bfloat162float(h));
}

__global__ void stack_bias(const float* __restrict__ phi_b, const float* __restrict__ g_b,
                           const float* __restrict__ theta_b)
{
    int i = threadIdx.x;
    d_c_bias[i] = (i < CI_) ? phi_b[i] : (i < 2 * CI_) ? g_b[i - CI_] : theta_b[i - 2 * CI_];
}

__global__ void transpose_split(const float* __restrict__ in,
                                __nv_bfloat16* __restrict__ hi, __nv_bfloat16* __restrict__ lo)
{
    __shared__ float t[32][33];
    int z  = blockIdx.z;
    int n0 = blockIdx.x * 32, c0 = blockIdx.y * 32;
    int tx = threadIdx.x, ty = threadIdx.y;
    const float* ip = in + (size_t)z * C_ * N_;
#pragma unroll
    for (int i = 0; i < 4; i++)
        t[ty + 8 * i][tx] = ip[(size_t)(c0 + ty + 8 * i) * N_ + n0 + tx];
    __syncthreads();
#pragma unroll
    for (int i = 0; i < 4; i++) {
        float v = t[tx][ty + 8 * i];
        __nv_bfloat16 h = __float2bfloat16(v);
        size_t o = ((size_t)z * N_ + n0 + ty + 8 * i) * C_ + c0 + tx;
        hi[o] = h;
        lo[o] = __float2bfloat16(v - __bfloat162float(h));
    }
}

// merged pool: threads 0-127 -> phi (cols 0-127, fp16); threads 128-255 -> g (cols 128-255, fp32)
__global__ void pool_both_k()
{
    int m = blockIdx.x, z = blockIdx.y;
    int tid = threadIdx.x;
    int ci  = tid & (CI_ - 1);
    int t  = m / (HS_ * WS_);
    int r  = m % (HS_ * WS_);
    int h2 = r / WS_, w2 = r % WS_;
    int n00 = t * (H_ * W_) + 2 * h2 * W_ + 2 * w2;
    const int ld = 2 * CI_;
    int col = (tid < CI_) ? ci : (CI_ + ci);
    const float* p = d_convN + (size_t)z * N_ * ld + col;
    float v = fmaxf(fmaxf(p[(size_t)n00 * ld],        p[(size_t)(n00 + 1) * ld]),
                    fmaxf(p[(size_t)(n00 + W_) * ld], p[(size_t)(n00 + W_ + 1) * ld]));
    if (tid < CI_)
        d_phiP[((size_t)z * NS_ + m) * CI_ + ci] = __float2half(v);
    else
        d_gpool[((size_t)z * NS_ + m) * CI_ + ci] = v;
}

__global__ void scale_tr_split_g()
{
    __shared__ float t[32][33];
    int z  = blockIdx.z;
    int m0 = blockIdx.x * 32, c0 = blockIdx.y * 32;
    int tx = threadIdx.x, ty = threadIdx.y;
#pragma unroll
    for (int i = 0; i < 4; i++)
        t[ty + 8 * i][tx] = d_gpool[((size_t)z * NS_ + m0 + ty + 8 * i) * CI_ + c0 + tx];
    __syncthreads();
    float inv = 1.0f / d_colsum[z * NS_ + m0 + tx];
#pragma unroll
    for (int i = 0; i < 4; i++) {
        float v = t[tx][ty + 8 * i] * inv;
        __nv_bfloat16 h = __float2bfloat16(v);
        size_t o = ((size_t)z * CI_ + c0 + ty + 8 * i) * NS_ + m0 + tx;
        d_gs_h[o] = h;
        d_gs_l[o] = __float2bfloat16(v - __bfloat162float(h));
    }
}

__global__ void y_convert()
{
    int i2 = blockIdx.x * 256 + threadIdx.x;
    if (i2 >= B_ * N_ * CI_ / 2) return;
    float2 v = *(const float2*)&d_yF[i2 * 2];
    store_split2(d_y_h, d_y_l, (size_t)i2 * 2, v.x, v.y);
}

__global__ void bn_finalize(const float* __restrict__ gamma, const float* __restrict__ beta)
{
    int c = threadIdx.x;
    float cnt  = (float)(B_ * N_);
    float mean = d_bnsum[c] / cnt;
    float var  = d_bnsumsq[c] / cnt - mean * mean;
    float inv  = rsqrtf(var + 1e-5f);
    float g    = gamma[c] * inv;
    d_bnscale[c] = g;
    d_bnbias[c]  = beta[c] - mean * g;
}

__global__ void final_kernel(const float* __restrict__ x, float* __restrict__ out)
{
    int idx4 = blockIdx.x * blockDim.x + threadIdx.x;
    if (idx4 >= (B_ * C_ * N_) / 4) return;
    int idx = idx4 * 4;
    int c = (idx / N_) % C_;
    float sc = d_bnscale[c], bi = d_bnbias[c];
    float4 w  = *(const float4*)&d_wy[idx];
    float4 xv = *(const float4*)&x[idx];
    float4 o;
    o.x = fmaf(w.x, sc, bi) + xv.x;
    o.y = fmaf(w.y, sc, bi) + xv.y;
    o.z = fmaf(w.z, sc, bi) + xv.z;
    o.w = fmaf(w.w, sc, bi) + xv.w;
    *(float4*)&out[idx] = o;
}

// ---------------- launch ---------------------------------------------------------
extern "C" void kernel_launch(void* const* d_in, const int* in_sizes, int n_in,
                              void* d_out, int out_size)
{
    const float* x       = (const float*)d_in[0];
    const float* mp      = (const float*)d_in[1];
    const float* g_w     = (const float*)d_in[2];
    const float* g_b     = (const float*)d_in[3];
    const float* theta_w = (const float*)d_in[4];
    const float* theta_b = (const float*)d_in[5];
    const float* phi_w   = (const float*)d_in[6];
    const float* phi_b   = (const float*)d_in[7];
    const float* W_w     = (const float*)d_in[8];
    const float* W_b     = (const float*)d_in[9];
    const float* gamma   = (const float*)d_in[10];
    const float* beta    = (const float*)d_in[11];
    float* out = (float*)d_out;

    __nv_bfloat16 *xT_h, *xT_l, *mT_h, *mT_l, *cw_h, *cw_l;
    __nv_bfloat16 *Ww_h, *Ww_l, *gs_h, *gs_l, *ef_h, *y_h, *y_l;
    __half *thT, *phiP;
    float *convN, *wy, *colsum, *c_bias, *yF, *bnsum, *bnsumsq;
    cudaGetSymbolAddress((void**)&xT_h, d_xT_h);   cudaGetSymbolAddress((void**)&xT_l, d_xT_l);
    cudaGetSymbolAddress((void**)&mT_h, d_mT_h);   cudaGetSymbolAddress((void**)&mT_l, d_mT_l);
    cudaGetSymbolAddress((void**)&cw_h, d_cw_h);   cudaGetSymbolAddress((void**)&cw_l, d_cw_l);
    cudaGetSymbolAddress((void**)&Ww_h, d_Ww_h);   cudaGetSymbolAddress((void**)&Ww_l, d_Ww_l);
    cudaGetSymbolAddress((void**)&thT, d_thT);     cudaGetSymbolAddress((void**)&phiP, d_phiP);
    cudaGetSymbolAddress((void**)&gs_h, d_gs_h);   cudaGetSymbolAddress((void**)&gs_l, d_gs_l);
    cudaGetSymbolAddress((void**)&ef_h, d_ef_h);
    cudaGetSymbolAddress((void**)&y_h, d_y_h);     cudaGetSymbolAddress((void**)&y_l, d_y_l);
    cudaGetSymbolAddress((void**)&convN, d_convN); cudaGetSymbolAddress((void**)&wy, d_wy);
    cudaGetSymbolAddress((void**)&colsum, d_colsum);
    cudaGetSymbolAddress((void**)&c_bias, d_c_bias);
    cudaGetSymbolAddress((void**)&yF, d_yF);
    cudaGetSymbolAddress((void**)&bnsum, d_bnsum);
    cudaGetSymbolAddress((void**)&bnsumsq, d_bnsumsq);

    cudaFuncSetAttribute((const void*)mma_gemm<6,0,0,0>, cudaFuncAttributeMaxDynamicSharedMemorySize, SMEM_TOT);
    cudaFuncSetAttribute((const void*)mma_gemm<2,1,1,1>, cudaFuncAttributeMaxDynamicSharedMemorySize, SMEM_TOT);
    cudaFuncSetAttribute((const void*)mma_gemm<3,1,0,0>, cudaFuncAttributeMaxDynamicSharedMemorySize, SMEM_TOT);
    cudaFuncSetAttribute((const void*)mma_gemm<4,0,0,0>, cudaFuncAttributeMaxDynamicSharedMemorySize, SMEM_TOT);

    // prep
    split_weights<<<dim3(128, 4), 256>>>(phi_w, g_w, theta_w, W_w);
    stack_bias<<<1, CW_>>>(phi_b, g_b, theta_b);
    transpose_split<<<dim3(N_ / 32, C_ / 32, B_), dim3(32, 8)>>>(x,  xT_h, xT_l);
    transpose_split<<<dim3(N_ / 32, C_ / 32, B_), dim3(32, 8)>>>(mp, mT_h, mT_l);
    // merged conv: fp32 phi|g (cols 0-255) + fp16 theta (cols 256-383 -> d_thT)
    mma_gemm<6,0,0,0><<<dim3(3, N_ / 128, B_), 256, SMEM_TOT>>>(
        xT_h, xT_l, mT_h, mT_l, 2 * CI_, (size_t)N_ * C_,
        cw_h, cw_l, 0,
        N_, CW_, C_, 1, c_bias, nullptr,
        convN, (__nv_bfloat16*)thT, nullptr, (size_t)N_ * 2 * CI_, 2 * CI_,
        nullptr, nullptr, nullptr);
    cudaMemsetAsync(colsum, 0, B_ * NS_ * sizeof(float));
    cudaMemsetAsync(yF, 0, B_ * N_ * CI_ * sizeof(float));
    cudaMemsetAsync(bnsum, 0, C_ * sizeof(float));
    cudaMemsetAsync(bnsumsq, 0, C_ * sizeof(float));
    // merged pools (phi fp16 + g fp32)
    pool_both_k<<<dim3(NS_, B_), 2 * CI_>>>();
    // f = exp(theta @ phi^T): fp16 single x single, colsum from quantized ef
    mma_gemm<2,1,1,1><<<dim3((NS_ + 127) / 128, N_ / 128, B_), 256, SMEM_TOT>>>(
        (const __nv_bfloat16*)thT, (const __nv_bfloat16*)thT,
        (const __nv_bfloat16*)thT, (const __nv_bfloat16*)thT, 1 << 30, (size_t)N_ * CI_,
        (const __nv_bfloat16*)phiP, (const __nv_bfloat16*)phiP, (size_t)NS_ * CI_,
        N_, NS_, CI_, 1, nullptr, nullptr,
        nullptr, ef_h, nullptr, (size_t)N_ * NS_, NS_, colsum, nullptr, nullptr);
    // g scaled by 1/Z, transposed, split bf16
    scale_tr_split_g<<<dim3(NS_ / 32, CI_ / 32, B_), dim3(32, 8)>>>();
    // y = ef @ gs^T: A single bf16 (2 products), split-K=7
    mma_gemm<3,1,0,0><<<dim3(7, N_ / 128, B_), 256, SMEM_TOT>>>(
        ef_h, ef_h, ef_h, ef_h, 1 << 30, (size_t)N_ * NS_,
        gs_h, gs_l, (size_t)CI_ * NS_,
        N_, CI_, NS_, 7, nullptr, nullptr,
        yF, nullptr, nullptr, (size_t)N_ * CI_, CI_, nullptr, nullptr, nullptr);
    // y -> split bf16
    y_convert<<<(B_ * N_ * CI_ / 2 + 255) / 256, 256>>>();
    // W_y = W_w @ y^T + W_b, fused BN stats
    mma_gemm<4,0,0,0><<<dim3(N_ / 128, C_ / 128, B_), 256, SMEM_TOT>>>(
        Ww_h, Ww_l, Ww_h, Ww_l, 1 << 30, (size_t)0,
        y_h, y_l, (size_t)N_ * CI_,
        C_, N_, CI_, 1, nullptr, W_b,
        wy, nullptr, nullptr, (size_t)C_ * N_, N_, nullptr, bnsum, bnsumsq);
    // BN finalize + residual
    bn_finalize<<<1, C_>>>(gamma, beta);
    final_kernel<<<(B_ * C_ * N_ / 4 + 255) / 256, 256>>>(x, out);
}

// round 17
// speedup vs baseline: 1.2789x; 1.0425x over previous
#include <cuda_runtime.h>
#include <cuda_bf16.h>
#include <cuda_fp16.h>
#include <cstdint>

#define B_   2
#define C_   256
#define CI_  128
#define T_   16
#define H_   28
#define W_   28
#define N_   12544
#define HS_  14
#define WS_  14
#define NS_  3136
#define CW_  (3*CI_)     // stacked conv output channels: [phi | g | theta]

typedef unsigned long long u64;

// ---------------- scratch (device globals) -------------------------------------
__device__ __align__(16) __half d_xT[B_*N_*C_];           // x transposed, single fp16
__device__ __align__(16) __half d_mT[B_*N_*C_];           // mask transposed, single fp16
__device__ __align__(16) __half d_cw_h[CW_*C_], d_cw_l[CW_*C_];   // conv weights split fp16
__device__ __align__(16) __nv_bfloat16 d_Ww_h[C_*CI_],    d_Ww_l[C_*CI_];
__device__ float d_c_bias[CW_];
__device__ __align__(16) float d_convN[B_*N_*2*CI_];      // (z, N, 256) fp32: phi|g
__device__ __align__(16) __half d_thT[B_*N_*CI_];         // theta fp16 (conv EPI 6)
__device__ __align__(16) __half d_phiP[B_*NS_*CI_];       // phi pooled fp16
__device__ __align__(16) float d_gpool[B_*NS_*CI_];
__device__ __align__(16) __nv_bfloat16 d_gs_h[B_*CI_*NS_], d_gs_l[B_*CI_*NS_];
__device__ __align__(16) __nv_bfloat16 d_ef_h[(size_t)B_*N_*NS_];   // exp(f) bf16 (157 MB)
__device__ float d_colsum[B_*NS_];
__device__ __align__(16) float d_yF[B_*N_*CI_];
__device__ __align__(16) __nv_bfloat16 d_y_h[B_*N_*CI_], d_y_l[B_*N_*CI_];
__device__ __align__(16) float d_wy[B_*C_*N_];
__device__ float d_bnsum[C_], d_bnsumsq[C_];
__device__ float d_bnscale[C_], d_bnbias[C_];

// ---------------- PTX helpers ---------------------------------------------------
__device__ __forceinline__ uint32_t smem_u32(const void* p) {
    uint32_t a;
    asm("{ .reg .u64 t; cvta.to.shared.u64 t, %1; cvt.u32.u64 %0, t; }" : "=r"(a) : "l"(p));
    return a;
}
__device__ __forceinline__ void cpa16(uint32_t d, const void* s, int sz) {
    asm volatile("cp.async.ca.shared.global [%0], [%1], 16, %2;" :: "r"(d), "l"(s), "r"(sz));
}
__device__ __forceinline__ void cp_commit() { asm volatile("cp.async.commit_group;" ::: "memory"); }
__device__ __forceinline__ void cp_wait0()  { asm volatile("cp.async.wait_group 0;"  ::: "memory"); }

__device__ __forceinline__ void ldm4(uint32_t* r, uint32_t a) {
    asm volatile("ldmatrix.sync.aligned.m8n8.x4.shared.b16 {%0,%1,%2,%3}, [%4];"
                 : "=r"(r[0]), "=r"(r[1]), "=r"(r[2]), "=r"(r[3]) : "r"(a));
}
__device__ __forceinline__ void mma_bf16(float* c, const uint32_t* a, uint32_t b0, uint32_t b1) {
    asm volatile("mma.sync.aligned.m16n8k16.row.col.f32.bf16.bf16.f32 "
                 "{%0,%1,%2,%3}, {%4,%5,%6,%7}, {%8,%9}, {%0,%1,%2,%3};"
                 : "+f"(c[0]), "+f"(c[1]), "+f"(c[2]), "+f"(c[3])
                 : "r"(a[0]), "r"(a[1]), "r"(a[2]), "r"(a[3]), "r"(b0), "r"(b1));
}
__device__ __forceinline__ void mma_fp16(float* c, const uint32_t* a, uint32_t b0, uint32_t b1) {
    asm volatile("mma.sync.aligned.m16n8k16.row.col.f32.f16.f16.f32 "
                 "{%0,%1,%2,%3}, {%4,%5,%6,%7}, {%8,%9}, {%0,%1,%2,%3};"
                 : "+f"(c[0]), "+f"(c[1]), "+f"(c[2]), "+f"(c[3])
                 : "r"(a[0]), "r"(a[1]), "r"(a[2]), "r"(a[3]), "r"(b0), "r"(b1));
}
__device__ __forceinline__ void mma_any(int HALF, float* c, const uint32_t* a,
                                        uint32_t b0, uint32_t b1) {
    if (HALF) mma_fp16(c, a, b0, b1);
    else      mma_bf16(c, a, b0, b1);
}
__device__ __forceinline__ void store_split2(__nv_bfloat16* hi, __nv_bfloat16* lo,
                                             size_t o, float v0, float v1) {
    __nv_bfloat16 h0 = __float2bfloat16(v0), h1 = __float2bfloat16(v1);
    __nv_bfloat162 hv; hv.x = h0; hv.y = h1;
    __nv_bfloat162 lv;
    lv.x = __float2bfloat16(v0 - __bfloat162float(h0));
    lv.y = __float2bfloat16(v1 - __bfloat162float(h1));
    *(__nv_bfloat162*)(hi + o) = hv;
    *(__nv_bfloat162*)(lo + o) = lv;
}

// ---------------- generic split HMMA GEMM ----------------------------------------
// AS: A single   BS: B single   HALF: all products fp16 (operands fp16); else bf16
// Dual-A: if j0 >= aSwitch, use (Ah2, Al2).
// EPI 0: fp32 store (+biasCol/+biasRow)
// EPI 2: exp -> bf16 quantize -> colsum atomics + staged bf16 store
// EPI 3: fp32 atomicAdd (split-K partials)
// EPI 4: fp32 store (+biasRow) + per-channel sum/sumsq atomics (fused BN stats)
// EPI 6: fp32 store for jg < 2*CI, fp16 store to outHi(__half, ld CI_) for jg >= 2*CI
#define TROW 80
#define TILE_BYTES (128*TROW)
#define OFF_AH 0
#define OFF_AL (TILE_BYTES)
#define OFF_BH (2*TILE_BYTES)
#define OFF_BL (3*TILE_BYTES)
#define BUF_BYTES (4*TILE_BYTES)
#define SMEM_TOT (2*BUF_BYTES)
#define EROW 136

template <int AS, int BS>
__device__ __forceinline__ void copy_chunk(uint32_t sb, int buf,
    const __nv_bfloat16* Ah, const __nv_bfloat16* Al, int i0,
    const __nv_bfloat16* Bh, const __nv_bfloat16* Bl, int j0, int Nn,
    int K, int k0, int tid)
{
    uint32_t base = sb + buf * BUF_BYTES;
#pragma unroll
    for (int i = 0; i < 2; i++) {
        int e = tid + i * 256;
        int r = e >> 2, seg = e & 3;
        uint32_t doff = r * TROW + seg * 16;
        size_t asrc = (size_t)(i0 + r) * K + k0 + seg * 8;
        cpa16(base + OFF_AH + doff, Ah + asrc, 16);
        if (!AS) cpa16(base + OFF_AL + doff, Al + asrc, 16);
        int brow = j0 + r;
        int sz = (brow < Nn) ? 16 : 0;
        int brc = (brow < Nn) ? brow : (Nn - 1);
        size_t bsrc = (size_t)brc * K + k0 + seg * 8;
        cpa16(base + OFF_BH + doff, Bh + bsrc, sz);
        if (!BS) cpa16(base + OFF_BL + doff, Bl + bsrc, sz);
    }
}

template <int EPI, int AS, int BS, int HALF>
__global__ void __launch_bounds__(256, 2)
mma_gemm(const __nv_bfloat16* __restrict__ Ah, const __nv_bfloat16* __restrict__ Al,
         const __nv_bfloat16* __restrict__ Ah2, const __nv_bfloat16* __restrict__ Al2,
         int aSwitch, size_t strA,
         const __nv_bfloat16* __restrict__ Bh, const __nv_bfloat16* __restrict__ Bl, size_t strB,
         int M, int Nn, int K, int ksplits,
         const float* __restrict__ biasCol, const float* __restrict__ biasRow,
         float* __restrict__ outF,
         __nv_bfloat16* __restrict__ outHi, __nv_bfloat16* __restrict__ outLo,
         size_t strO, int ldO,
         float* __restrict__ colsum,
         float* __restrict__ bnsum, float* __restrict__ bnsumsq)
{
    extern __shared__ __align__(128) char smem[];
    const uint32_t sb = smem_u32(smem);
    const int tid = threadIdx.x, lane = tid & 31, wid = tid >> 5;
    const int wm = wid >> 2, wn = wid & 3;
    const int z  = blockIdx.z;
    const int ksid = blockIdx.x % ksplits;
    const int i0 = blockIdx.y * 128, j0 = (blockIdx.x / ksplits) * 128;
    const int kLen = K / ksplits;
    const int kOff = ksid * kLen;

    const __nv_bfloat16* Asel_h = (j0 >= aSwitch) ? Ah2 : Ah;
    const __nv_bfloat16* Asel_l = (j0 >= aSwitch) ? Al2 : Al;
    const __nv_bfloat16* Ahz = Asel_h + (size_t)z * strA;
    const __nv_bfloat16* Alz = Asel_l + (size_t)z * strA;
    const __nv_bfloat16* Bhz = Bh + (size_t)z * strB;
    const __nv_bfloat16* Blz = Bl + (size_t)z * strB;

    float acc[4][4][4];
#pragma unroll
    for (int a = 0; a < 4; a++)
#pragma unroll
        for (int b = 0; b < 4; b++)
#pragma unroll
            for (int c = 0; c < 4; c++) acc[a][b][c] = 0.f;

    const uint32_t aBase = sb + (uint32_t)((wm * 64 + (lane & 15)) * TROW + (lane >> 4) * 16);
    const uint32_t bBase = sb + (uint32_t)((wn * 32 + (lane & 7) + ((lane & 16) ? 8 : 0)) * TROW
                                           + ((lane & 8) ? 16 : 0));

    const int nch = kLen / 32;
    copy_chunk<AS, BS>(sb, 0, Ahz, Alz, i0, Bhz, Blz, j0, Nn, K, kOff, tid);
    cp_commit();
    for (int ch = 0; ch < nch; ch++) {
        cp_wait0();
        __syncthreads();
        if (ch + 1 < nch) {
            copy_chunk<AS, BS>(sb, (ch + 1) & 1, Ahz, Alz, i0, Bhz, Blz, j0, Nn, K,
                               kOff + (ch + 1) * 32, tid);
            cp_commit();
        }
        const uint32_t buf = (uint32_t)((ch & 1) * BUF_BYTES);
#pragma unroll
        for (int ks = 0; ks < 2; ks++) {
            uint32_t bh[8], bl[8];
#pragma unroll
            for (int grp = 0; grp < 2; grp++) {
                ldm4(&bh[grp * 4], bBase + buf + OFF_BH + grp * (16 * TROW) + ks * 32);
                if (!BS)
                    ldm4(&bl[grp * 4], bBase + buf + OFF_BL + grp * (16 * TROW) + ks * 32);
            }
#pragma unroll
            for (int am = 0; am < 4; am++) {
                uint32_t ah4[4], al4[4];
                ldm4(ah4, aBase + buf + OFF_AH + am * (16 * TROW) + ks * 32);
                if (!AS)
                    ldm4(al4, aBase + buf + OFF_AL + am * (16 * TROW) + ks * 32);
#pragma unroll
                for (int bn = 0; bn < 4; bn++)
                    mma_any(HALF, acc[am][bn], ah4, bh[bn * 2], bh[bn * 2 + 1]);
                if (!BS) {
#pragma unroll
                    for (int bn = 0; bn < 4; bn++)
                        mma_any(HALF, acc[am][bn], ah4, bl[bn * 2], bl[bn * 2 + 1]);
                }
                if (!AS) {
#pragma unroll
                    for (int bn = 0; bn < 4; bn++)
                        mma_any(HALF, acc[am][bn], al4, bh[bn * 2], bh[bn * 2 + 1]);
                }
            }
        }
    }

    // ---- epilogue ----
    const int q    = lane >> 2;
    const int rloc = wm * 64 + q;
    const int cloc = wn * 32 + (lane & 3) * 2;

    if (EPI == 2) {
        __syncthreads();
        __nv_bfloat16* sh = (__nv_bfloat16*)smem;
        float cs[4][2];
#pragma unroll
        for (int bn = 0; bn < 4; bn++) { cs[bn][0] = 0.f; cs[bn][1] = 0.f; }
#pragma unroll
        for (int am = 0; am < 4; am++) {
            int rl = rloc + am * 16;
#pragma unroll
            for (int bn = 0; bn < 4; bn++) {
                int jl = cloc + bn * 8;
                __nv_bfloat16 h0 = __float2bfloat16(__expf(acc[am][bn][0]));
                __nv_bfloat16 h1 = __float2bfloat16(__expf(acc[am][bn][1]));
                __nv_bfloat16 h2 = __float2bfloat16(__expf(acc[am][bn][2]));
                __nv_bfloat16 h3 = __float2bfloat16(__expf(acc[am][bn][3]));
                cs[bn][0] += __bfloat162float(h0) + __bfloat162float(h2);
                cs[bn][1] += __bfloat162float(h1) + __bfloat162float(h3);
                __nv_bfloat162 hv01; hv01.x = h0; hv01.y = h1;
                __nv_bfloat162 hv23; hv23.x = h2; hv23.y = h3;
                *(__nv_bfloat162*)&sh[rl * EROW + jl]       = hv01;
                *(__nv_bfloat162*)&sh[(rl + 8) * EROW + jl] = hv23;
            }
        }
#pragma unroll
        for (int bn = 0; bn < 4; bn++)
#pragma unroll
            for (int jj = 0; jj < 2; jj++) {
                float v = cs[bn][jj];
                v += __shfl_xor_sync(0xffffffffu, v, 4);
                v += __shfl_xor_sync(0xffffffffu, v, 8);
                v += __shfl_xor_sync(0xffffffffu, v, 16);
                if (q == 0) {
                    int jg = j0 + cloc + bn * 8 + jj;
                    if (jg < Nn) atomicAdd(&colsum[z * Nn + jg], v);
                }
            }
        __syncthreads();
#pragma unroll
        for (int it = 0; it < 8; it++) {
            int e = it * 256 + tid;
            int r = e >> 4, s = e & 15;
            int jg = j0 + s * 8;
            if (jg < Nn) {
                size_t o = (size_t)z * strO + (size_t)(i0 + r) * ldO + jg;
                *(uint4*)(outHi + o) = *(const uint4*)&sh[r * EROW + s * 8];
            }
        }
    } else if (EPI == 3) {
#pragma unroll
        for (int am = 0; am < 4; am++) {
            int ig0 = i0 + rloc + am * 16;
#pragma unroll
            for (int bn = 0; bn < 4; bn++) {
                int jg = j0 + cloc + bn * 8;
                if (jg < Nn) {
                    size_t o0 = (size_t)z * strO + (size_t)ig0 * ldO + jg;
                    atomicAdd(outF + o0,     acc[am][bn][0]);
                    atomicAdd(outF + o0 + 1, acc[am][bn][1]);
                    atomicAdd(outF + o0 + (size_t)8 * ldO,     acc[am][bn][2]);
                    atomicAdd(outF + o0 + (size_t)8 * ldO + 1, acc[am][bn][3]);
                }
            }
        }
    } else if (EPI == 6) {
        __half* outH = (__half*)outHi;
#pragma unroll
        for (int am = 0; am < 4; am++) {
            int ig0 = i0 + rloc + am * 16;
#pragma unroll
            for (int bn = 0; bn < 4; bn++) {
                int jg = j0 + cloc + bn * 8;
                float bc0 = biasCol[jg];
                float bc1 = biasCol[jg + 1];
                float v0 = acc[am][bn][0] + bc0;
                float v1 = acc[am][bn][1] + bc1;
                float v2 = acc[am][bn][2] + bc0;
                float v3 = acc[am][bn][3] + bc1;
                if (jg < 2 * CI_) {
                    size_t o0 = (size_t)z * strO + (size_t)ig0 * ldO + jg;
                    *(float2*)(outF + o0) = make_float2(v0, v1);
                    *(float2*)(outF + o0 + (size_t)8 * ldO) = make_float2(v2, v3);
                } else {
                    int jc = jg - 2 * CI_;
                    size_t o0 = ((size_t)z * M + ig0) * CI_ + jc;
                    __half2 h01; h01.x = __float2half(v0); h01.y = __float2half(v1);
                    __half2 h23; h23.x = __float2half(v2); h23.y = __float2half(v3);
                    *(__half2*)(outH + o0) = h01;
                    *(__half2*)(outH + o0 + (size_t)8 * CI_) = h23;
                }
            }
        }
    } else {  // EPI 0 / 4
#pragma unroll
        for (int am = 0; am < 4; am++) {
            int ig0 = i0 + rloc + am * 16;
            float br0 = biasRow ? biasRow[ig0]     : 0.f;
            float br1 = biasRow ? biasRow[ig0 + 8] : 0.f;
            float sA = 0.f, sqA = 0.f, sB = 0.f, sqB = 0.f;
#pragma unroll
            for (int bn = 0; bn < 4; bn++) {
                int jg = j0 + cloc + bn * 8;
                if (jg < Nn) {
                    float bc0 = biasCol ? biasCol[jg]     : 0.f;
                    float bc1 = biasCol ? biasCol[jg + 1] : 0.f;
                    float v0 = acc[am][bn][0] + bc0 + br0;
                    float v1 = acc[am][bn][1] + bc1 + br0;
                    float v2 = acc[am][bn][2] + bc0 + br1;
                    float v3 = acc[am][bn][3] + bc1 + br1;
                    size_t o0 = (size_t)z * strO + (size_t)ig0 * ldO + jg;
                    *(float2*)(outF + o0) = make_float2(v0, v1);
                    *(float2*)(outF + o0 + (size_t)8 * ldO) = make_float2(v2, v3);
                    if (EPI == 4) {
                        sA += v0 + v1;  sqA += v0 * v0 + v1 * v1;
                        sB += v2 + v3;  sqB += v2 * v2 + v3 * v3;
                    }
                }
            }
            if (EPI == 4) {
                sA  += __shfl_xor_sync(0xffffffffu, sA, 1);
                sA  += __shfl_xor_sync(0xffffffffu, sA, 2);
                sqA += __shfl_xor_sync(0xffffffffu, sqA, 1);
                sqA += __shfl_xor_sync(0xffffffffu, sqA, 2);
                sB  += __shfl_xor_sync(0xffffffffu, sB, 1);
                sB  += __shfl_xor_sync(0xffffffffu, sB, 2);
                sqB += __shfl_xor_sync(0xffffffffu, sqB, 1);
                sqB += __shfl_xor_sync(0xffffffffu, sqB, 2);
                if ((lane & 3) == 0) {
                    atomicAdd(&bnsum[ig0],       sA);
                    atomicAdd(&bnsumsq[ig0],     sqA);
                    atomicAdd(&bnsum[ig0 + 8],   sB);
                    atomicAdd(&bnsumsq[ig0 + 8], sqB);
                }
            }
        }
    }
}

// ---------------- prep / pool / BN kernels --------------------------------------
// which 0-2: conv weights -> split fp16; which 3: W_w -> split bf16
__global__ void split_weights(const float* __restrict__ p_w, const float* __restrict__ g_w,
                              const float* __restrict__ t_w, const float* __restrict__ W_w)
{
    int i = blockIdx.x * 256 + threadIdx.x;
    int which = blockIdx.y;
    if (which == 3) {
        float v = W_w[i];
        __nv_bfloat16 h = __float2bfloat16(v);
        d_Ww_h[i] = h;
        d_Ww_l[i] = __float2bfloat16(v - __bfloat162float(h));
    } else {
        const float* in = (which == 0) ? p_w : (which == 1) ? g_w : t_w;
        float v = in[i];
        __half h = __float2half(v);
        d_cw_h[which * CI_ * C_ + i] = h;
        d_cw_l[which * CI_ * C_ + i] = __float2half(v - __half2float(h));
    }
}

__global__ void stack_bias(const float* __restrict__ phi_b, const float* __restrict__ g_b,
                           const float* __restrict__ theta_b)
{
    int i = threadIdx.x;
    d_c_bias[i] = (i < CI_) ? phi_b[i] : (i < 2 * CI_) ? g_b[i - CI_] : theta_b[i - 2 * CI_];
}

// (z, C, N) fp32 -> (z, N, C) single fp16
__global__ void transpose_half(const float* __restrict__ in, __half* __restrict__ outH)
{
    __shared__ float t[32][33];
    int z  = blockIdx.z;
    int n0 = blockIdx.x * 32, c0 = blockIdx.y * 32;
    int tx = threadIdx.x, ty = threadIdx.y;
    const float* ip = in + (size_t)z * C_ * N_;
#pragma unroll
    for (int i = 0; i < 4; i++)
        t[ty + 8 * i][tx] = ip[(size_t)(c0 + ty + 8 * i) * N_ + n0 + tx];
    __syncthreads();
#pragma unroll
    for (int i = 0; i < 4; i++) {
        size_t o = ((size_t)z * N_ + n0 + ty + 8 * i) * C_ + c0 + tx;
        outH[o] = __float2half(t[tx][ty + 8 * i]);
    }
}

// merged pool: threads 0-127 -> phi (fp16); threads 128-255 -> g (fp32)
__global__ void pool_both_k()
{
    int m = blockIdx.x, z = blockIdx.y;
    int tid = threadIdx.x;
    int ci  = tid & (CI_ - 1);
    int t  = m / (HS_ * WS_);
    int r  = m % (HS_ * WS_);
    int h2 = r / WS_, w2 = r % WS_;
    int n00 = t * (H_ * W_) + 2 * h2 * W_ + 2 * w2;
    const int ld = 2 * CI_;
    int col = (tid < CI_) ? ci : (CI_ + ci);
    const float* p = d_convN + (size_t)z * N_ * ld + col;
    float v = fmaxf(fmaxf(p[(size_t)n00 * ld],        p[(size_t)(n00 + 1) * ld]),
                    fmaxf(p[(size_t)(n00 + W_) * ld], p[(size_t)(n00 + W_ + 1) * ld]));
    if (tid < CI_)
        d_phiP[((size_t)z * NS_ + m) * CI_ + ci] = __float2half(v);
    else
        d_gpool[((size_t)z * NS_ + m) * CI_ + ci] = v;
}

__global__ void scale_tr_split_g()
{
    __shared__ float t[32][33];
    int z  = blockIdx.z;
    int m0 = blockIdx.x * 32, c0 = blockIdx.y * 32;
    int tx = threadIdx.x, ty = threadIdx.y;
#pragma unroll
    for (int i = 0; i < 4; i++)
        t[ty + 8 * i][tx] = d_gpool[((size_t)z * NS_ + m0 + ty + 8 * i) * CI_ + c0 + tx];
    __syncthreads();
    float inv = 1.0f / d_colsum[z * NS_ + m0 + tx];
#pragma unroll
    for (int i = 0; i < 4; i++) {
        float v = t[tx][ty + 8 * i] * inv;
        __nv_bfloat16 h = __float2bfloat16(v);
        size_t o = ((size_t)z * CI_ + c0 + ty + 8 * i) * NS_ + m0 + tx;
        d_gs_h[o] = h;
        d_gs_l[o] = __float2bfloat16(v - __bfloat162float(h));
    }
}

__global__ void y_convert()
{
    int i2 = blockIdx.x * 256 + threadIdx.x;
    if (i2 >= B_ * N_ * CI_ / 2) return;
    float2 v = *(const float2*)&d_yF[i2 * 2];
    store_split2(d_y_h, d_y_l, (size_t)i2 * 2, v.x, v.y);
}

__global__ void bn_finalize(const float* __restrict__ gamma, const float* __restrict__ beta)
{
    int c = threadIdx.x;
    float cnt  = (float)(B_ * N_);
    float mean = d_bnsum[c] / cnt;
    float var  = d_bnsumsq[c] / cnt - mean * mean;
    float inv  = rsqrtf(var + 1e-5f);
    float g    = gamma[c] * inv;
    d_bnscale[c] = g;
    d_bnbias[c]  = beta[c] - mean * g;
}

__global__ void final_kernel(const float* __restrict__ x, float* __restrict__ out)
{
    int idx4 = blockIdx.x * blockDim.x + threadIdx.x;
    if (idx4 >= (B_ * C_ * N_) / 4) return;
    int idx = idx4 * 4;
    int c = (idx / N_) % C_;
    float sc = d_bnscale[c], bi = d_bnbias[c];
    float4 w  = *(const float4*)&d_wy[idx];
    float4 xv = *(const float4*)&x[idx];
    float4 o;
    o.x = fmaf(w.x, sc, bi) + xv.x;
    o.y = fmaf(w.y, sc, bi) + xv.y;
    o.z = fmaf(w.z, sc, bi) + xv.z;
    o.w = fmaf(w.w, sc, bi) + xv.w;
    *(float4*)&out[idx] = o;
}

// ---------------- launch ---------------------------------------------------------
extern "C" void kernel_launch(void* const* d_in, const int* in_sizes, int n_in,
                              void* d_out, int out_size)
{
    const float* x       = (const float*)d_in[0];
    const float* mp      = (const float*)d_in[1];
    const float* g_w     = (const float*)d_in[2];
    const float* g_b     = (const float*)d_in[3];
    const float* theta_w = (const float*)d_in[4];
    const float* theta_b = (const float*)d_in[5];
    const float* phi_w   = (const float*)d_in[6];
    const float* phi_b   = (const float*)d_in[7];
    const float* W_w     = (const float*)d_in[8];
    const float* W_b     = (const float*)d_in[9];
    const float* gamma   = (const float*)d_in[10];
    const float* beta    = (const float*)d_in[11];
    float* out = (float*)d_out;

    __nv_bfloat16 *Ww_h, *Ww_l, *gs_h, *gs_l, *ef_h, *y_h, *y_l;
    __half *xT, *mT, *cw_h, *cw_l, *thT, *phiP;
    float *convN, *wy, *colsum, *c_bias, *yF, *bnsum, *bnsumsq;
    cudaGetSymbolAddress((void**)&xT, d_xT);       cudaGetSymbolAddress((void**)&mT, d_mT);
    cudaGetSymbolAddress((void**)&cw_h, d_cw_h);   cudaGetSymbolAddress((void**)&cw_l, d_cw_l);
    cudaGetSymbolAddress((void**)&Ww_h, d_Ww_h);   cudaGetSymbolAddress((void**)&Ww_l, d_Ww_l);
    cudaGetSymbolAddress((void**)&thT, d_thT);     cudaGetSymbolAddress((void**)&phiP, d_phiP);
    cudaGetSymbolAddress((void**)&gs_h, d_gs_h);   cudaGetSymbolAddress((void**)&gs_l, d_gs_l);
    cudaGetSymbolAddress((void**)&ef_h, d_ef_h);
    cudaGetSymbolAddress((void**)&y_h, d_y_h);     cudaGetSymbolAddress((void**)&y_l, d_y_l);
    cudaGetSymbolAddress((void**)&convN, d_convN); cudaGetSymbolAddress((void**)&wy, d_wy);
    cudaGetSymbolAddress((void**)&colsum, d_colsum);
    cudaGetSymbolAddress((void**)&c_bias, d_c_bias);
    cudaGetSymbolAddress((void**)&yF, d_yF);
    cudaGetSymbolAddress((void**)&bnsum, d_bnsum);
    cudaGetSymbolAddress((void**)&bnsumsq, d_bnsumsq);

    cudaFuncSetAttribute((const void*)mma_gemm<6,1,0,1>, cudaFuncAttributeMaxDynamicSharedMemorySize, SMEM_TOT);
    cudaFuncSetAttribute((const void*)mma_gemm<2,1,1,1>, cudaFuncAttributeMaxDynamicSharedMemorySize, SMEM_TOT);
    cudaFuncSetAttribute((const void*)mma_gemm<3,1,0,0>, cudaFuncAttributeMaxDynamicSharedMemorySize, SMEM_TOT);
    cudaFuncSetAttribute((const void*)mma_gemm<4,0,0,0>, cudaFuncAttributeMaxDynamicSharedMemorySize, SMEM_TOT);

    // prep
    split_weights<<<dim3(128, 4), 256>>>(phi_w, g_w, theta_w, W_w);
    stack_bias<<<1, CW_>>>(phi_b, g_b, theta_b);
    transpose_half<<<dim3(N_ / 32, C_ / 32, B_), dim3(32, 8)>>>(x,  xT);
    transpose_half<<<dim3(N_ / 32, C_ / 32, B_), dim3(32, 8)>>>(mp, mT);
    // merged conv (fp16, A single x B split -> 2 products):
    // fp32 phi|g (cols 0-255) + fp16 theta (cols 256-383 -> d_thT)
    mma_gemm<6,1,0,1><<<dim3(3, N_ / 128, B_), 256, SMEM_TOT>>>(
        (const __nv_bfloat16*)xT, (const __nv_bfloat16*)xT,
        (const __nv_bfloat16*)mT, (const __nv_bfloat16*)mT, 2 * CI_, (size_t)N_ * C_,
        (const __nv_bfloat16*)cw_h, (const __nv_bfloat16*)cw_l, 0,
        N_, CW_, C_, 1, c_bias, nullptr,
        convN, (__nv_bfloat16*)thT, nullptr, (size_t)N_ * 2 * CI_, 2 * CI_,
        nullptr, nullptr, nullptr);
    cudaMemsetAsync(colsum, 0, B_ * NS_ * sizeof(float));
    cudaMemsetAsync(yF, 0, B_ * N_ * CI_ * sizeof(float));
    cudaMemsetAsync(bnsum, 0, C_ * sizeof(float));
    cudaMemsetAsync(bnsumsq, 0, C_ * sizeof(float));
    // merged pools (phi fp16 + g fp32)
    pool_both_k<<<dim3(NS_, B_), 2 * CI_>>>();
    // f = exp(theta @ phi^T): fp16 single x single, colsum from quantized ef
    mma_gemm<2,1,1,1><<<dim3((NS_ + 127) / 128, N_ / 128, B_), 256, SMEM_TOT>>>(
        (const __nv_bfloat16*)thT, (const __nv_bfloat16*)thT,
        (const __nv_bfloat16*)thT, (const __nv_bfloat16*)thT, 1 << 30, (size_t)N_ * CI_,
        (const __nv_bfloat16*)phiP, (const __nv_bfloat16*)phiP, (size_t)NS_ * CI_,
        N_, NS_, CI_, 1, nullptr, nullptr,
        nullptr, ef_h, nullptr, (size_t)N_ * NS_, NS_, colsum, nullptr, nullptr);
    // g scaled by 1/Z, transposed, split bf16
    scale_tr_split_g<<<dim3(NS_ / 32, CI_ / 32, B_), dim3(32, 8)>>>();
    // y = ef @ gs^T: A single bf16 (2 products), split-K=7
    mma_gemm<3,1,0,0><<<dim3(7, N_ / 128, B_), 256, SMEM_TOT>>>(
        ef_h, ef_h, ef_h, ef_h, 1 << 30, (size_t)N_ * NS_,
        gs_h, gs_l, (size_t)CI_ * NS_,
        N_, CI_, NS_, 7, nullptr, nullptr,
        yF, nullptr, nullptr, (size_t)N_ * CI_, CI_, nullptr, nullptr, nullptr);
    // y -> split bf16
    y_convert<<<(B_ * N_ * CI_ / 2 + 255) / 256, 256>>>();
    // W_y = W_w @ y^T + W_b, fused BN stats
    mma_gemm<4,0,0,0><<<dim3(N_ / 128, C_ / 128, B_), 256, SMEM_TOT>>>(
        Ww_h, Ww_l, Ww_h, Ww_l, 1 << 30, (size_t)0,
        y_h, y_l, (size_t)N_ * CI_,
        C_, N_, CI_, 1, nullptr, W_b,
        wy, nullptr, nullptr, (size_t)C_ * N_, N_, nullptr, bnsum, bnsumsq);
    // BN finalize + residual
    bn_finalize<<<1, C_>>>(gamma, beta);
    final_kernel<<<(B_ * C_ * N_ / 4 + 255) / 256, 256>>>(x, out);
}